// round 2
// baseline (speedup 1.0000x reference)
#include <cuda_runtime.h>
#include <math.h>

#define B_    2
#define N_    1024
#define HID   2048
#define H_    32
#define D_    64
#define HKV   8
#define GROUPS 4
#define CHUNK 64
#define NC    16
#define TOK   (B_ * N_)     // 2048 tokens
#define QDIM  (H_ * D_)     // 2048
#define KDIM  (HKV * D_)    // 512

// ---------------- scratch (device globals; no allocation allowed) ----------------
__device__ float g_q[TOK * QDIM];     // raw q projection, token-major [t][h*64+d]
__device__ float g_k[TOK * KDIM];     // raw k projection [t][hkv*64+d]
__device__ float g_v[TOK * KDIM];
__device__ float g_ql[TOK * QDIM];    // softmax(q) features
__device__ float g_kl[TOK * KDIM];    // softmax(k) features
__device__ float g_beta[TOK * KDIM];  // log_sigmoid(k)/16
__device__ float g_olin[TOK * QDIM];  // delta-rule branch output (token-major)
__device__ float g_omix[TOK * QDIM];  // o_base then mixed

// ---------------- generic fp32 tiled GEMM: C[M,N] = A[M,K] @ B[K,N] --------------
// BM=BN=128, BK=8, 256 threads, 8x8 per thread. M,N,K all multiples of tile dims here.
__global__ void sgemm128(const float* __restrict__ A, const float* __restrict__ B,
                         float* __restrict__ C, int M, int N, int K) {
    __shared__ float As[8][128];
    __shared__ float Bs[8][128];
    const int tid  = threadIdx.x;
    const int cRow = blockIdx.y * 128;
    const int cCol = blockIdx.x * 128;
    const int ty   = (tid / 16) * 8;
    const int tx   = (tid % 16) * 8;
    const int aRow = tid >> 1, aCol = (tid & 1) << 2;    // 128x8 A tile, float4
    const int bRow = tid >> 5, bCol = (tid & 31) << 2;   // 8x128 B tile, float4
    const float* Ap = A + (size_t)(cRow + aRow) * K + aCol;
    const float* Bp = B + (size_t)bRow * N + cCol + bCol;
    float acc[8][8];
#pragma unroll
    for (int i = 0; i < 8; ++i)
#pragma unroll
        for (int j = 0; j < 8; ++j) acc[i][j] = 0.f;

    for (int k0 = 0; k0 < K; k0 += 8) {
        float4 a4 = *(const float4*)Ap;
        As[aCol + 0][aRow] = a4.x;
        As[aCol + 1][aRow] = a4.y;
        As[aCol + 2][aRow] = a4.z;
        As[aCol + 3][aRow] = a4.w;
        *(float4*)&Bs[bRow][bCol] = *(const float4*)Bp;
        __syncthreads();
#pragma unroll
        for (int kk = 0; kk < 8; ++kk) {
            float ar[8], br[8];
#pragma unroll
            for (int i = 0; i < 8; ++i) ar[i] = As[kk][ty + i];
#pragma unroll
            for (int j = 0; j < 8; ++j) br[j] = Bs[kk][tx + j];
#pragma unroll
            for (int i = 0; i < 8; ++i)
#pragma unroll
                for (int j = 0; j < 8; ++j) acc[i][j] += ar[i] * br[j];
        }
        __syncthreads();
        Ap += 8;
        Bp += (size_t)8 * N;
    }
#pragma unroll
    for (int i = 0; i < 8; ++i) {
        float* Cr = C + (size_t)(cRow + ty + i) * N + cCol + tx;
#pragma unroll
        for (int j = 0; j < 8; j += 4) {
            float4 v4 = make_float4(acc[i][j], acc[i][j + 1], acc[i][j + 2], acc[i][j + 3]);
            *(float4*)(Cr + j) = v4;
        }
    }
}

// ------------- feature kernel: softmax rows of 64 + log-sigmoid gate -------------
// warp per row. rows: [0, TOK*H_)  -> g_q  -> g_ql
//                [TOK*H_, +TOK*HKV) -> g_k -> g_kl and g_beta
__global__ void feat_kernel() {
    const int wg   = (blockIdx.x * blockDim.x + threadIdx.x) >> 5;
    const int lane = threadIdx.x & 31;
    if (wg < TOK * H_) {
        const float* src = g_q + (size_t)wg * 64;
        float x0 = src[lane], x1 = src[lane + 32];
        float m = fmaxf(x0, x1);
#pragma unroll
        for (int o = 16; o; o >>= 1) m = fmaxf(m, __shfl_xor_sync(0xffffffffu, m, o));
        float e0 = __expf(x0 - m), e1 = __expf(x1 - m);
        float s = e0 + e1;
#pragma unroll
        for (int o = 16; o; o >>= 1) s += __shfl_xor_sync(0xffffffffu, s, o);
        float inv = 1.f / s;
        float* dst = g_ql + (size_t)wg * 64;
        dst[lane] = e0 * inv;
        dst[lane + 32] = e1 * inv;
    } else {
        const int r = wg - TOK * H_;
        if (r < TOK * HKV) {
            const float* src = g_k + (size_t)r * 64;
            float x0 = src[lane], x1 = src[lane + 32];
            float m = fmaxf(x0, x1);
#pragma unroll
            for (int o = 16; o; o >>= 1) m = fmaxf(m, __shfl_xor_sync(0xffffffffu, m, o));
            float e0 = __expf(x0 - m), e1 = __expf(x1 - m);
            float s = e0 + e1;
#pragma unroll
            for (int o = 16; o; o >>= 1) s += __shfl_xor_sync(0xffffffffu, s, o);
            float inv = 1.f / s;
            float* dst = g_kl + (size_t)r * 64;
            dst[lane] = e0 * inv;
            dst[lane + 32] = e1 * inv;
            // log_sigmoid(x)/16 = (min(x,0) - log1p(exp(-|x|)))/16
            float b0 = (fminf(x0, 0.f) - log1pf(__expf(-fabsf(x0)))) * 0.0625f;
            float b1 = (fminf(x1, 0.f) - log1pf(__expf(-fabsf(x1)))) * 0.0625f;
            float* bd = g_beta + (size_t)r * 64;
            bd[lane] = b0;
            bd[lane + 32] = b1;
        }
    }
}

// ----------------------- delta-rule chunked scan, block per (b,h) ----------------
// dynamic smem: 6 arrays of 64x65 floats: S, Q, Kc, W(k_beta->w), U(v_beta->u->u_p), L
#define PAD 65
__global__ void delta_kernel() {
    extern __shared__ float sm[];
    float* S  = sm;
    float* Q  = S  + 64 * PAD;
    float* Kc = Q  + 64 * PAD;
    float* W  = Kc + 64 * PAD;
    float* U  = W  + 64 * PAD;
    float* L  = U  + 64 * PAD;

    const int tid = threadIdx.x;          // 512
    const int bh  = blockIdx.x;           // 0..63
    const int b = bh >> 5, h = bh & 31, hkv = h >> 2;
    const int e  = tid & 63;              // column
    const int r0 = (tid >> 6) * 8;        // 8 rows per thread

    for (int idx = tid; idx < 4096; idx += 512) S[(idx >> 6) * PAD + (idx & 63)] = 0.f;
    __syncthreads();

    for (int ch = 0; ch < NC; ++ch) {
        const int n0 = ch * CHUNK;
        // ---- load chunk tiles ----
        for (int idx = tid; idx < 4096; idx += 512) {
            int c = idx >> 6, d = idx & 63;
            int t = b * N_ + n0 + c;
            float kv = g_kl[(size_t)t * KDIM + hkv * 64 + d];
            float bt = g_beta[(size_t)t * KDIM + hkv * 64 + d];
            float vv = g_v[(size_t)t * KDIM + hkv * 64 + d];
            Kc[c * PAD + d] = kv;
            W[c * PAD + d]  = kv * bt;   // k_beta
            U[c * PAD + d]  = vv * bt;   // v_beta
            Q[c * PAD + d]  = g_ql[(size_t)t * QDIM + h * 64 + d];
        }
        __syncthreads();

        // ---- L = strict_tril(k_beta @ k^T) ----
        {
            float acc[8];
#pragma unroll
            for (int i = 0; i < 8; ++i) acc[i] = 0.f;
            for (int d = 0; d < 64; ++d) {
                float kb = Kc[e * PAD + d];
#pragma unroll
                for (int i = 0; i < 8; ++i) acc[i] += W[(r0 + i) * PAD + d] * kb;
            }
#pragma unroll
            for (int i = 0; i < 8; ++i)
                L[(r0 + i) * PAD + e] = (e < r0 + i) ? acc[i] : 0.f;
        }
        __syncthreads();

        // ---- forward substitution: U = T@v_beta, W = T@k_beta (in place) ----
        for (int j = 0; j < 63; ++j) {
            float uj = U[j * PAD + e];
            float wj = W[j * PAD + e];
            for (int i = j + 1 + (tid >> 6); i < 64; i += 8) {
                float lij = L[i * PAD + j];
                U[i * PAD + e] -= lij * uj;
                W[i * PAD + e] -= lij * wj;
            }
            __syncthreads();
        }

        // ---- u_p = U - W @ S (in place on U), and attn = causal(Q @ Kc^T) in L ----
        {
            float acc[8];
#pragma unroll
            for (int i = 0; i < 8; ++i) acc[i] = 0.f;
            for (int d = 0; d < 64; ++d) {
                float s = S[d * PAD + e];
#pragma unroll
                for (int i = 0; i < 8; ++i) acc[i] += W[(r0 + i) * PAD + d] * s;
            }
#pragma unroll
            for (int i = 0; i < 8; ++i) U[(r0 + i) * PAD + e] -= acc[i];
        }
        {
            float acc[8];
#pragma unroll
            for (int i = 0; i < 8; ++i) acc[i] = 0.f;
            for (int d = 0; d < 64; ++d) {
                float kb = Kc[e * PAD + d];
#pragma unroll
                for (int i = 0; i < 8; ++i) acc[i] += Q[(r0 + i) * PAD + d] * kb;
            }
#pragma unroll
            for (int i = 0; i < 8; ++i)
                L[(r0 + i) * PAD + e] = (e <= r0 + i) ? acc[i] : 0.f;
        }
        __syncthreads();

        // ---- o = Q @ S + attn @ u_p  ->  g_olin ----
        {
            float acc[8];
#pragma unroll
            for (int i = 0; i < 8; ++i) acc[i] = 0.f;
            for (int d = 0; d < 64; ++d) {
                float s = S[d * PAD + e];
#pragma unroll
                for (int i = 0; i < 8; ++i) acc[i] += Q[(r0 + i) * PAD + d] * s;
            }
            for (int j = 0; j < 64; ++j) {
                float u = U[j * PAD + e];
#pragma unroll
                for (int i = 0; i < 8; ++i) acc[i] += L[(r0 + i) * PAD + j] * u;
            }
#pragma unroll
            for (int i = 0; i < 8; ++i)
                g_olin[(size_t)(b * N_ + n0 + r0 + i) * QDIM + h * 64 + e] = acc[i];
        }
        __syncthreads();

        // ---- S += Kc^T @ u_p ----
        {
            float acc[8];
#pragma unroll
            for (int i = 0; i < 8; ++i) acc[i] = 0.f;
            for (int c = 0; c < 64; ++c) {
                float u = U[c * PAD + e];
#pragma unroll
                for (int i = 0; i < 8; ++i) acc[i] += Kc[c * PAD + r0 + i] * u;
            }
#pragma unroll
            for (int i = 0; i < 8; ++i) S[(r0 + i) * PAD + e] += acc[i];
        }
        __syncthreads();
    }
}

// --------------- base causal attention: block per (row i, head bh) ---------------
// writes normalized attn row to d_out attn region, accumulates o_base into g_omix
__global__ void base_attn_kernel(float* __restrict__ attnw) {
    __shared__ float sc[N_];
    __shared__ float qrow[64];
    __shared__ float red[256];
    const int i   = blockIdx.x;
    const int bh  = blockIdx.y;
    const int b = bh >> 5, h = bh & 31, hkv = h >> 2;
    const int tid = threadIdx.x;
    const int lane = tid & 31, warp = tid >> 5;
    const int ti = b * N_ + i;

    if (tid < 64) qrow[tid] = g_q[(size_t)ti * QDIM + h * 64 + tid];
    __syncthreads();

    const float scale = 0.125f;  // 1/sqrt(64)
    for (int j = warp; j <= i; j += 8) {
        const float* kr = g_k + (size_t)(b * N_ + j) * KDIM + hkv * 64;
        float p = qrow[lane] * kr[lane] + qrow[lane + 32] * kr[lane + 32];
#pragma unroll
        for (int o = 16; o; o >>= 1) p += __shfl_xor_sync(0xffffffffu, p, o);
        if (lane == 0) sc[j] = p * scale;
    }
    __syncthreads();

    float m = -1e30f;
    for (int j = tid; j <= i; j += 256) m = fmaxf(m, sc[j]);
    red[tid] = m;
    __syncthreads();
    for (int s = 128; s; s >>= 1) {
        if (tid < s) red[tid] = fmaxf(red[tid], red[tid + s]);
        __syncthreads();
    }
    m = red[0];
    __syncthreads();

    float lsum = 0.f;
    for (int j = tid; j <= i; j += 256) {
        float ev = __expf(sc[j] - m);
        sc[j] = ev;
        lsum += ev;
    }
    red[tid] = lsum;
    __syncthreads();
    for (int s = 128; s; s >>= 1) {
        if (tid < s) red[tid] += red[tid + s];
        __syncthreads();
    }
    float inv = 1.f / red[0];
    __syncthreads();
    for (int j = tid; j <= i; j += 256) sc[j] *= inv;
    __syncthreads();

    if (attnw) {
        float* arow = attnw + ((size_t)bh * N_ + i) * N_;
        for (int j = tid; j < N_; j += 256) arow[j] = (j <= i) ? sc[j] : 0.f;
    }

    // o_base
    const int d = tid & 63, part = tid >> 6;
    float acc = 0.f;
    for (int j = part; j <= i; j += 4)
        acc += sc[j] * g_v[(size_t)(b * N_ + j) * KDIM + hkv * 64 + d];
    red[tid] = acc;
    __syncthreads();
    if (tid < 64) {
        float o = red[tid] + red[tid + 64] + red[tid + 128] + red[tid + 192];
        g_omix[(size_t)ti * QDIM + h * 64 + tid] = o;
    }
}

// ------------- mix: omix = 0.5*o_lin + 0.5*o_base (MAG = 0.5) --------------------
__global__ void combine_kernel() {
    int i = blockIdx.x * 256 + threadIdx.x;
    g_omix[i] = 0.5f * g_omix[i] + 0.5f * g_olin[i];
}

// ------------------------------------ launch -------------------------------------
extern "C" void kernel_launch(void* const* d_in, const int* in_sizes, int n_in,
                              void* d_out, int out_size) {
    const float* hs = (const float*)d_in[0];
    const float* Wq = (const float*)d_in[1];
    const float* Wk = (const float*)d_in[2];
    const float* Wv = (const float*)d_in[3];
    const float* Wo = (const float*)d_in[4];
    float* out = (float*)d_out;

    const size_t out_elems  = (size_t)TOK * QDIM;                  // 4,194,304
    const size_t attn_elems = (size_t)B_ * H_ * N_ * N_;           // 67,108,864
    float* attnw = ((size_t)out_size >= out_elems + attn_elems) ? (out + out_elems)
                                                                : nullptr;

    float *qp, *kp, *vp, *omixp;
    cudaGetSymbolAddress((void**)&qp, g_q);
    cudaGetSymbolAddress((void**)&kp, g_k);
    cudaGetSymbolAddress((void**)&vp, g_v);
    cudaGetSymbolAddress((void**)&omixp, g_omix);

    // projections
    sgemm128<<<dim3(QDIM / 128, TOK / 128), 256>>>(hs, Wq, qp, TOK, QDIM, HID);
    sgemm128<<<dim3(KDIM / 128, TOK / 128), 256>>>(hs, Wk, kp, TOK, KDIM, HID);
    sgemm128<<<dim3(KDIM / 128, TOK / 128), 256>>>(hs, Wv, vp, TOK, KDIM, HID);

    // feature maps + gate: one warp per row, 81920 rows total
    {
        const int total_warps = TOK * H_ + TOK * HKV;   // 81920
        const int blocks = (total_warps * 32 + 255) / 256;  // 10240
        feat_kernel<<<blocks, 256>>>();
    }

    // delta-rule scan (one block per (b,h))
    cudaFuncSetAttribute(delta_kernel, cudaFuncAttributeMaxDynamicSharedMemorySize,
                         6 * 64 * PAD * (int)sizeof(float));
    delta_kernel<<<64, 512, 6 * 64 * PAD * sizeof(float)>>>();

    // base attention (writes attn weights + o_base)
    base_attn_kernel<<<dim3(N_, B_ * H_), 256>>>(attnw);

    // mix branches, then output projection
    combine_kernel<<<TOK * QDIM / 256, 256>>>();
    sgemm128<<<dim3(QDIM / 128, TOK / 128), 256>>>(omixp, Wo, out, TOK, QDIM, HID);
}

// round 3
// speedup vs baseline: 1.1979x; 1.1979x over previous
#include <cuda_runtime.h>
#include <math.h>

#define B_    2
#define N_    1024
#define HID   2048
#define H_    32
#define D_    64
#define HKV   8
#define CHUNK 64
#define NC    16
#define TOK   (B_ * N_)     // 2048 tokens
#define QDIM  (H_ * D_)     // 2048
#define KDIM  (HKV * D_)    // 512

// ---------------- scratch (device globals; no allocation allowed) ----------------
__device__ float g_q[TOK * QDIM];
__device__ float g_k[TOK * KDIM];
__device__ float g_v[TOK * KDIM];
__device__ float g_ql[TOK * QDIM];
__device__ float g_kl[TOK * KDIM];
__device__ float g_beta[TOK * KDIM];
__device__ float g_olin[TOK * QDIM];
__device__ float g_omix[TOK * QDIM];

// =============== fp32 GEMM body: 128x128 tile, BK=16, double-buffered =============
// 256 threads; per-thread 8x8 micro-tile in split fragments (rows ty*4 / ty*4+64,
// cols tx*4 / tx*4+64). 1 __syncthreads per k-iter.
struct SmemGemm {
    float As[2][16][128];
    float Bs[2][16][128];
};

__device__ __forceinline__ void gemm_body(const float* __restrict__ A,
                                          const float* __restrict__ B,
                                          float* __restrict__ C,
                                          int N, int K, int cRow, int cCol,
                                          SmemGemm* sm) {
    const int tid = threadIdx.x;
    const int ty = tid >> 4, tx = tid & 15;

    // A tile loader: thread -> row tid/2, col (tid&1)*8 (two float4)
    const int aRow = tid >> 1;
    const int aCol = (tid & 1) << 3;
    const float* Aptr = A + (size_t)(cRow + aRow) * K + aCol;
    // B tile loader: f = tid -> row f>>5, col (f&31)*4; second at +8 rows
    const int bRow = tid >> 5;
    const int bCol = (tid & 31) << 2;
    const float* Bptr = B + (size_t)bRow * N + cCol + bCol;

    float acc[8][8];
#pragma unroll
    for (int i = 0; i < 8; ++i)
#pragma unroll
        for (int j = 0; j < 8; ++j) acc[i][j] = 0.f;

    float4 a0, a1, b0, b1;
    // preload tile 0
    a0 = *(const float4*)(Aptr);
    a1 = *(const float4*)(Aptr + 4);
    b0 = *(const float4*)(Bptr);
    b1 = *(const float4*)(Bptr + (size_t)8 * N);
    {
        float* As0 = &sm->As[0][0][0];
        As0[(aCol + 0) * 128 + aRow] = a0.x;
        As0[(aCol + 1) * 128 + aRow] = a0.y;
        As0[(aCol + 2) * 128 + aRow] = a0.z;
        As0[(aCol + 3) * 128 + aRow] = a0.w;
        As0[(aCol + 4) * 128 + aRow] = a1.x;
        As0[(aCol + 5) * 128 + aRow] = a1.y;
        As0[(aCol + 6) * 128 + aRow] = a1.z;
        As0[(aCol + 7) * 128 + aRow] = a1.w;
        *(float4*)&sm->Bs[0][bRow][bCol] = b0;
        *(float4*)&sm->Bs[0][bRow + 8][bCol] = b1;
    }
    __syncthreads();

    const int T = K >> 4;
    for (int kt = 0; kt < T; ++kt) {
        const int cur = kt & 1;
        if (kt + 1 < T) {
            const float* Ap = Aptr + (kt + 1) * 16;
            const float* Bp = Bptr + (size_t)(kt + 1) * 16 * N;
            a0 = *(const float4*)(Ap);
            a1 = *(const float4*)(Ap + 4);
            b0 = *(const float4*)(Bp);
            b1 = *(const float4*)(Bp + (size_t)8 * N);
        }
        const float* Asc = &sm->As[cur][0][0];
        const float* Bsc = &sm->Bs[cur][0][0];
#pragma unroll
        for (int kk = 0; kk < 16; ++kk) {
            float4 ra0 = *(const float4*)(Asc + kk * 128 + ty * 4);
            float4 ra1 = *(const float4*)(Asc + kk * 128 + ty * 4 + 64);
            float4 rb0 = *(const float4*)(Bsc + kk * 128 + tx * 4);
            float4 rb1 = *(const float4*)(Bsc + kk * 128 + tx * 4 + 64);
            float ar[8] = {ra0.x, ra0.y, ra0.z, ra0.w, ra1.x, ra1.y, ra1.z, ra1.w};
            float br[8] = {rb0.x, rb0.y, rb0.z, rb0.w, rb1.x, rb1.y, rb1.z, rb1.w};
#pragma unroll
            for (int i = 0; i < 8; ++i)
#pragma unroll
                for (int j = 0; j < 8; ++j) acc[i][j] += ar[i] * br[j];
        }
        if (kt + 1 < T) {
            const int nxt = cur ^ 1;
            float* Asn = &sm->As[nxt][0][0];
            Asn[(aCol + 0) * 128 + aRow] = a0.x;
            Asn[(aCol + 1) * 128 + aRow] = a0.y;
            Asn[(aCol + 2) * 128 + aRow] = a0.z;
            Asn[(aCol + 3) * 128 + aRow] = a0.w;
            Asn[(aCol + 4) * 128 + aRow] = a1.x;
            Asn[(aCol + 5) * 128 + aRow] = a1.y;
            Asn[(aCol + 6) * 128 + aRow] = a1.z;
            Asn[(aCol + 7) * 128 + aRow] = a1.w;
            *(float4*)&sm->Bs[nxt][bRow][bCol] = b0;
            *(float4*)&sm->Bs[nxt][bRow + 8][bCol] = b1;
            __syncthreads();
        }
    }

    // write C: rows {ty*4+i, ty*4+64+i}, col groups {tx*4, tx*4+64}
#pragma unroll
    for (int g = 0; g < 2; ++g) {
#pragma unroll
        for (int i = 0; i < 4; ++i) {
            const int r = ty * 4 + g * 64 + i;
            float* Cr = C + (size_t)(cRow + r) * N + cCol;
            *(float4*)(Cr + tx * 4) =
                make_float4(acc[g * 4 + i][0], acc[g * 4 + i][1], acc[g * 4 + i][2], acc[g * 4 + i][3]);
            *(float4*)(Cr + tx * 4 + 64) =
                make_float4(acc[g * 4 + i][4], acc[g * 4 + i][5], acc[g * 4 + i][6], acc[g * 4 + i][7]);
        }
    }
}

__global__ void sgemm_v2(const float* __restrict__ A, const float* __restrict__ B,
                         float* __restrict__ C, int N, int K) {
    __shared__ SmemGemm sm;
    gemm_body(A, B, C, N, K, blockIdx.y * 128, blockIdx.x * 128, &sm);
}

// fused K|V projection: grid.x = 8; blocks 0-3 -> Wk/g_k, 4-7 -> Wv/g_v (N=512 each)
__global__ void kv_gemm(const float* __restrict__ A, const float* __restrict__ Wk,
                        const float* __restrict__ Wv) {
    __shared__ SmemGemm sm;
    int bx = blockIdx.x;
    const float* Bm;
    float* Cm;
    if (bx < 4) { Bm = Wk; Cm = g_k; }
    else        { Bm = Wv; Cm = g_v; bx -= 4; }
    gemm_body(A, Bm, Cm, KDIM, HID, blockIdx.y * 128, bx * 128, &sm);
}

// ------------- feature kernel: softmax rows of 64 + log-sigmoid gate -------------
__global__ void feat_kernel() {
    const int wg   = (blockIdx.x * blockDim.x + threadIdx.x) >> 5;
    const int lane = threadIdx.x & 31;
    if (wg < TOK * H_) {
        const float* src = g_q + (size_t)wg * 64;
        float x0 = src[lane], x1 = src[lane + 32];
        float m = fmaxf(x0, x1);
#pragma unroll
        for (int o = 16; o; o >>= 1) m = fmaxf(m, __shfl_xor_sync(0xffffffffu, m, o));
        float e0 = __expf(x0 - m), e1 = __expf(x1 - m);
        float s = e0 + e1;
#pragma unroll
        for (int o = 16; o; o >>= 1) s += __shfl_xor_sync(0xffffffffu, s, o);
        float inv = 1.f / s;
        float* dst = g_ql + (size_t)wg * 64;
        dst[lane] = e0 * inv;
        dst[lane + 32] = e1 * inv;
    } else {
        const int r = wg - TOK * H_;
        if (r < TOK * HKV) {
            const float* src = g_k + (size_t)r * 64;
            float x0 = src[lane], x1 = src[lane + 32];
            float m = fmaxf(x0, x1);
#pragma unroll
            for (int o = 16; o; o >>= 1) m = fmaxf(m, __shfl_xor_sync(0xffffffffu, m, o));
            float e0 = __expf(x0 - m), e1 = __expf(x1 - m);
            float s = e0 + e1;
#pragma unroll
            for (int o = 16; o; o >>= 1) s += __shfl_xor_sync(0xffffffffu, s, o);
            float inv = 1.f / s;
            float* dst = g_kl + (size_t)r * 64;
            dst[lane] = e0 * inv;
            dst[lane + 32] = e1 * inv;
            float b0 = (fminf(x0, 0.f) - log1pf(__expf(-fabsf(x0)))) * 0.0625f;
            float b1 = (fminf(x1, 0.f) - log1pf(__expf(-fabsf(x1)))) * 0.0625f;
            float* bd = g_beta + (size_t)r * 64;
            bd[lane] = b0;
            bd[lane + 32] = b1;
        }
    }
}

// ----------------------- delta-rule chunked scan, block per (b,h) ----------------
#define PAD 65
__global__ void delta_kernel() {
    extern __shared__ float sm[];
    float* S  = sm;
    float* Q  = S  + 64 * PAD;
    float* Kc = Q  + 64 * PAD;
    float* W  = Kc + 64 * PAD;
    float* U  = W  + 64 * PAD;
    float* L  = U  + 64 * PAD;

    const int tid = threadIdx.x;          // 512
    const int bh  = blockIdx.x;           // 0..63
    const int b = bh >> 5, h = bh & 31, hkv = h >> 2;
    const int e  = tid & 63;
    const int r0 = (tid >> 6) * 8;

    for (int idx = tid; idx < 4096; idx += 512) S[(idx >> 6) * PAD + (idx & 63)] = 0.f;
    __syncthreads();

    for (int ch = 0; ch < NC; ++ch) {
        const int n0 = ch * CHUNK;
        for (int idx = tid; idx < 4096; idx += 512) {
            int c = idx >> 6, d = idx & 63;
            int t = b * N_ + n0 + c;
            float kv = g_kl[(size_t)t * KDIM + hkv * 64 + d];
            float bt = g_beta[(size_t)t * KDIM + hkv * 64 + d];
            float vv = g_v[(size_t)t * KDIM + hkv * 64 + d];
            Kc[c * PAD + d] = kv;
            W[c * PAD + d]  = kv * bt;
            U[c * PAD + d]  = vv * bt;
            Q[c * PAD + d]  = g_ql[(size_t)t * QDIM + h * 64 + d];
        }
        __syncthreads();

        {   // L = strict_tril(k_beta @ k^T)
            float acc[8];
#pragma unroll
            for (int i = 0; i < 8; ++i) acc[i] = 0.f;
            for (int d = 0; d < 64; ++d) {
                float kb = Kc[e * PAD + d];
#pragma unroll
                for (int i = 0; i < 8; ++i) acc[i] += W[(r0 + i) * PAD + d] * kb;
            }
#pragma unroll
            for (int i = 0; i < 8; ++i)
                L[(r0 + i) * PAD + e] = (e < r0 + i) ? acc[i] : 0.f;
        }
        __syncthreads();

        // forward substitution on U and W
        for (int j = 0; j < 63; ++j) {
            float uj = U[j * PAD + e];
            float wj = W[j * PAD + e];
            for (int i = j + 1 + (tid >> 6); i < 64; i += 8) {
                float lij = L[i * PAD + j];
                U[i * PAD + e] -= lij * uj;
                W[i * PAD + e] -= lij * wj;
            }
            __syncthreads();
        }

        {   // u_p = U - W @ S
            float acc[8];
#pragma unroll
            for (int i = 0; i < 8; ++i) acc[i] = 0.f;
            for (int d = 0; d < 64; ++d) {
                float s = S[d * PAD + e];
#pragma unroll
                for (int i = 0; i < 8; ++i) acc[i] += W[(r0 + i) * PAD + d] * s;
            }
#pragma unroll
            for (int i = 0; i < 8; ++i) U[(r0 + i) * PAD + e] -= acc[i];
        }
        {   // attn = causal(Q @ Kc^T) into L
            float acc[8];
#pragma unroll
            for (int i = 0; i < 8; ++i) acc[i] = 0.f;
            for (int d = 0; d < 64; ++d) {
                float kb = Kc[e * PAD + d];
#pragma unroll
                for (int i = 0; i < 8; ++i) acc[i] += Q[(r0 + i) * PAD + d] * kb;
            }
#pragma unroll
            for (int i = 0; i < 8; ++i)
                L[(r0 + i) * PAD + e] = (e <= r0 + i) ? acc[i] : 0.f;
        }
        __syncthreads();

        {   // o = Q @ S + attn @ u_p
            float acc[8];
#pragma unroll
            for (int i = 0; i < 8; ++i) acc[i] = 0.f;
            for (int d = 0; d < 64; ++d) {
                float s = S[d * PAD + e];
#pragma unroll
                for (int i = 0; i < 8; ++i) acc[i] += Q[(r0 + i) * PAD + d] * s;
            }
            for (int j = 0; j < 64; ++j) {
                float u = U[j * PAD + e];
#pragma unroll
                for (int i = 0; i < 8; ++i) acc[i] += L[(r0 + i) * PAD + j] * u;
            }
#pragma unroll
            for (int i = 0; i < 8; ++i)
                g_olin[(size_t)(b * N_ + n0 + r0 + i) * QDIM + h * 64 + e] = acc[i];
        }
        __syncthreads();

        {   // S += Kc^T @ u_p
            float acc[8];
#pragma unroll
            for (int i = 0; i < 8; ++i) acc[i] = 0.f;
            for (int c = 0; c < 64; ++c) {
                float u = U[c * PAD + e];
#pragma unroll
                for (int i = 0; i < 8; ++i) acc[i] += Kc[c * PAD + r0 + i] * u;
            }
#pragma unroll
            for (int i = 0; i < 8; ++i) S[(r0 + i) * PAD + e] += acc[i];
        }
        __syncthreads();
    }
}

// --------------- base causal attention: block per (row i, head bh) ---------------
// writes normalized attn row; epilogue mixes o_base with g_olin into g_omix
__global__ void base_attn_kernel(float* __restrict__ attnw) {
    __shared__ float sc[N_];
    __shared__ float qrow[64];
    __shared__ float red[256];
    const int i   = blockIdx.x;
    const int bh  = blockIdx.y;
    const int b = bh >> 5, h = bh & 31, hkv = h >> 2;
    const int tid = threadIdx.x;
    const int lane = tid & 31, warp = tid >> 5;
    const int ti = b * N_ + i;

    if (tid < 64) qrow[tid] = g_q[(size_t)ti * QDIM + h * 64 + tid];
    __syncthreads();

    const float scale = 0.125f;
    for (int j = warp; j <= i; j += 8) {
        const float* kr = g_k + (size_t)(b * N_ + j) * KDIM + hkv * 64;
        float p = qrow[lane] * kr[lane] + qrow[lane + 32] * kr[lane + 32];
#pragma unroll
        for (int o = 16; o; o >>= 1) p += __shfl_xor_sync(0xffffffffu, p, o);
        if (lane == 0) sc[j] = p * scale;
    }
    __syncthreads();

    float m = -1e30f;
    for (int j = tid; j <= i; j += 256) m = fmaxf(m, sc[j]);
    red[tid] = m;
    __syncthreads();
    for (int s = 128; s; s >>= 1) {
        if (tid < s) red[tid] = fmaxf(red[tid], red[tid + s]);
        __syncthreads();
    }
    m = red[0];
    __syncthreads();

    float lsum = 0.f;
    for (int j = tid; j <= i; j += 256) {
        float ev = __expf(sc[j] - m);
        sc[j] = ev;
        lsum += ev;
    }
    red[tid] = lsum;
    __syncthreads();
    for (int s = 128; s; s >>= 1) {
        if (tid < s) red[tid] += red[tid + s];
        __syncthreads();
    }
    float inv = 1.f / red[0];
    __syncthreads();
    for (int j = tid; j <= i; j += 256) sc[j] *= inv;
    __syncthreads();

    if (attnw) {
        float* arow = attnw + ((size_t)bh * N_ + i) * N_;
        for (int j = tid; j < N_; j += 256) arow[j] = (j <= i) ? sc[j] : 0.f;
    }

    const int d = tid & 63, part = tid >> 6;
    float acc = 0.f;
    for (int j = part; j <= i; j += 4)
        acc += sc[j] * g_v[(size_t)(b * N_ + j) * KDIM + hkv * 64 + d];
    red[tid] = acc;
    __syncthreads();
    if (tid < 64) {
        float o = red[tid] + red[tid + 64] + red[tid + 128] + red[tid + 192];
        // mix with linear branch here (MAG = 0.5)
        float mix = 0.5f * o + 0.5f * g_olin[(size_t)ti * QDIM + h * 64 + tid];
        g_omix[(size_t)ti * QDIM + h * 64 + tid] = mix;
    }
}

// ------------------------------------ launch -------------------------------------
extern "C" void kernel_launch(void* const* d_in, const int* in_sizes, int n_in,
                              void* d_out, int out_size) {
    const float* hs = (const float*)d_in[0];
    const float* Wq = (const float*)d_in[1];
    const float* Wk = (const float*)d_in[2];
    const float* Wv = (const float*)d_in[3];
    const float* Wo = (const float*)d_in[4];
    float* out = (float*)d_out;

    const size_t out_elems  = (size_t)TOK * QDIM;
    const size_t attn_elems = (size_t)B_ * H_ * N_ * N_;
    float* attnw = ((size_t)out_size >= out_elems + attn_elems) ? (out + out_elems)
                                                                : nullptr;

    float *qp, *omixp;
    cudaGetSymbolAddress((void**)&qp, g_q);
    cudaGetSymbolAddress((void**)&omixp, g_omix);

    // projections
    sgemm_v2<<<dim3(QDIM / 128, TOK / 128), 256>>>(hs, Wq, qp, QDIM, HID);
    kv_gemm<<<dim3(8, TOK / 128), 256>>>(hs, Wk, Wv);

    // feature maps + gate: one warp per row, 81920 rows total
    {
        const int total_warps = TOK * H_ + TOK * HKV;       // 81920
        const int blocks = (total_warps * 32 + 255) / 256;  // 10240
        feat_kernel<<<blocks, 256>>>();
    }

    // delta-rule scan (one block per (b,h))
    cudaFuncSetAttribute(delta_kernel, cudaFuncAttributeMaxDynamicSharedMemorySize,
                         6 * 64 * PAD * (int)sizeof(float));
    delta_kernel<<<64, 512, 6 * 64 * PAD * sizeof(float)>>>();

    // base attention (writes attn weights + mixed o into g_omix)
    base_attn_kernel<<<dim3(N_, B_ * H_), 256>>>(attnw);

    // output projection on mixed features
    sgemm_v2<<<dim3(QDIM / 128, TOK / 128), 256>>>(omixp, Wo, out, QDIM, HID);
}

// round 5
// speedup vs baseline: 1.3987x; 1.1676x over previous
#include <cuda_runtime.h>
#include <cuda_bf16.h>
#include <math.h>
#include <stdint.h>

typedef __nv_bfloat16 bf16;
typedef unsigned int u32;

#define B_    2
#define N_    1024
#define HID   2048
#define H_    32
#define D_    64
#define HKV   8
#define CHUNK 64
#define NC    16
#define TOK   (B_ * N_)
#define QDIM  (H_ * D_)
#define KDIM  (HKV * D_)
#define PAD   65

// ---------------- fp32 scratch ----------------
__device__ float g_q[TOK * QDIM];
__device__ float g_k[TOK * KDIM];
__device__ float g_v[TOK * KDIM];
__device__ float g_ql[TOK * QDIM];
__device__ float g_kl[TOK * KDIM];
__device__ float g_beta[TOK * KDIM];
__device__ float g_olin[TOK * QDIM];
__device__ float g_omix[TOK * QDIM];
__device__ float g_W[B_ * H_ * NC * 64 * 64];
__device__ float g_U[B_ * H_ * NC * 64 * 64];
__device__ float g_A[B_ * H_ * NC * 64 * 64];
// bf16 split scratch
__device__ bf16 g_hsh[TOK * HID];
__device__ bf16 g_hsl[TOK * HID];
__device__ bf16 g_wqh[HID * QDIM];
__device__ bf16 g_wql[HID * QDIM];
__device__ bf16 g_wkh[HID * KDIM];
__device__ bf16 g_wkl[HID * KDIM];
__device__ bf16 g_wvh[HID * KDIM];
__device__ bf16 g_wvl[HID * KDIM];
__device__ bf16 g_woh[QDIM * HID];
__device__ bf16 g_wol[QDIM * HID];
__device__ bf16 g_oxh[TOK * QDIM];
__device__ bf16 g_oxl[TOK * QDIM];

// ---------------- split fp32 -> bf16 hi/lo ----------------
__global__ void split_kernel(const float* __restrict__ src, bf16* __restrict__ hi,
                             bf16* __restrict__ lo, int n) {
    int i = blockIdx.x * 256 + threadIdx.x;
    if (i < n) {
        float x = src[i];
        bf16 hv = __float2bfloat16(x);
        hi[i] = hv;
        lo[i] = __float2bfloat16(x - __bfloat162float(hv));
    }
}

// ---------------- mma wrappers ----------------
__device__ __forceinline__ void ldsm_x4(u32* r, u32 addr) {
    asm volatile("ldmatrix.sync.aligned.m8n8.x4.shared.b16 {%0,%1,%2,%3}, [%4];"
                 : "=r"(r[0]), "=r"(r[1]), "=r"(r[2]), "=r"(r[3]) : "r"(addr));
}
__device__ __forceinline__ void ldsm_x4t(u32* r, u32 addr) {
    asm volatile("ldmatrix.sync.aligned.m8n8.x4.trans.shared.b16 {%0,%1,%2,%3}, [%4];"
                 : "=r"(r[0]), "=r"(r[1]), "=r"(r[2]), "=r"(r[3]) : "r"(addr));
}
__device__ __forceinline__ void mma_bf16(float* c, const u32* a, const u32* b) {
    asm volatile(
        "mma.sync.aligned.m16n8k16.row.col.f32.bf16.bf16.f32 "
        "{%0,%1,%2,%3}, {%4,%5,%6,%7}, {%8,%9}, {%0,%1,%2,%3};"
        : "+f"(c[0]), "+f"(c[1]), "+f"(c[2]), "+f"(c[3])
        : "r"(a[0]), "r"(a[1]), "r"(a[2]), "r"(a[3]), "r"(b[0]), "r"(b[1]));
}

// C[M,N] ~= AhBh + AlBh + AhBl, fp32 out. 128x128 tile, BK=32, 256 thr (4x2 warps).
#define ASTRIDE 40
#define BSTRIDE 136
__global__ void bgemm(const bf16* __restrict__ Ah, const bf16* __restrict__ Al,
                      const bf16* __restrict__ Bh, const bf16* __restrict__ Bl,
                      float* __restrict__ C, int N, int K) {
    __shared__ bf16 sAh[128 * ASTRIDE];
    __shared__ bf16 sAl[128 * ASTRIDE];
    __shared__ bf16 sBh[32 * BSTRIDE];
    __shared__ bf16 sBl[32 * BSTRIDE];

    const int tid = threadIdx.x;
    const int lane = tid & 31;
    const int wid = tid >> 5;
    const int warp_m = wid & 3;
    const int warp_n = wid >> 2;
    const int cRow = blockIdx.y * 128;
    const int cCol = blockIdx.x * 128;

    const int aRow = tid >> 1;
    const int aKc = (tid & 1) * 16;
    const int bK = tid >> 3;
    const int bNc = (tid & 7) * 16;
    const bf16* ApH = Ah + (size_t)(cRow + aRow) * K + aKc;
    const bf16* ApL = Al + (size_t)(cRow + aRow) * K + aKc;
    const bf16* BpH = Bh + (size_t)bK * N + cCol + bNc;
    const bf16* BpL = Bl + (size_t)bK * N + cCol + bNc;

    u32 sAh_u = (u32)__cvta_generic_to_shared(sAh);
    u32 sAl_u = (u32)__cvta_generic_to_shared(sAl);
    u32 sBh_u = (u32)__cvta_generic_to_shared(sBh);
    u32 sBl_u = (u32)__cvta_generic_to_shared(sBl);

    float acc[2][8][4];
#pragma unroll
    for (int mt = 0; mt < 2; ++mt) {
#pragma unroll
        for (int nt = 0; nt < 8; ++nt) {
#pragma unroll
            for (int i = 0; i < 4; ++i) acc[mt][nt][i] = 0.f;
        }
    }

    const int T = K >> 5;
    for (int kt = 0; kt < T; ++kt) {
        uint4 ah0 = *(const uint4*)(ApH + (size_t)kt * 32);
        uint4 ah1 = *(const uint4*)(ApH + (size_t)kt * 32 + 8);
        uint4 al0 = *(const uint4*)(ApL + (size_t)kt * 32);
        uint4 al1 = *(const uint4*)(ApL + (size_t)kt * 32 + 8);
        uint4 bh0 = *(const uint4*)(BpH + (size_t)kt * 32 * N);
        uint4 bh1 = *(const uint4*)(BpH + (size_t)kt * 32 * N + 8);
        uint4 bl0 = *(const uint4*)(BpL + (size_t)kt * 32 * N);
        uint4 bl1 = *(const uint4*)(BpL + (size_t)kt * 32 * N + 8);
        __syncthreads();
        *(uint4*)(sAh + aRow * ASTRIDE + aKc)     = ah0;
        *(uint4*)(sAh + aRow * ASTRIDE + aKc + 8) = ah1;
        *(uint4*)(sAl + aRow * ASTRIDE + aKc)     = al0;
        *(uint4*)(sAl + aRow * ASTRIDE + aKc + 8) = al1;
        *(uint4*)(sBh + bK * BSTRIDE + bNc)       = bh0;
        *(uint4*)(sBh + bK * BSTRIDE + bNc + 8)   = bh1;
        *(uint4*)(sBl + bK * BSTRIDE + bNc)       = bl0;
        *(uint4*)(sBl + bK * BSTRIDE + bNc + 8)   = bl1;
        __syncthreads();

#pragma unroll
        for (int kk = 0; kk < 32; kk += 16) {
            u32 a_h[2][4];
            u32 a_l[2][4];
            u32 b_h[8][2];
            u32 b_l[8][2];
#pragma unroll
            for (int mt = 0; mt < 2; ++mt) {
                int row = warp_m * 32 + mt * 16 + (lane & 15);
                u32 off = (u32)((row * ASTRIDE + kk + (lane >> 4) * 8) * 2);
                ldsm_x4(a_h[mt], sAh_u + off);
                ldsm_x4(a_l[mt], sAl_u + off);
            }
#pragma unroll
            for (int p = 0; p < 4; ++p) {
                int colbase = warp_n * 64 + p * 16;
                int krow = kk + (lane & 7) + ((lane >> 3) & 1) * 8;
                int col = colbase + ((lane >> 4) & 1) * 8;
                u32 off = (u32)((krow * BSTRIDE + col) * 2);
                u32 r[4];
                ldsm_x4t(r, sBh_u + off);
                b_h[2 * p][0] = r[0];
                b_h[2 * p][1] = r[1];
                b_h[2 * p + 1][0] = r[2];
                b_h[2 * p + 1][1] = r[3];
                ldsm_x4t(r, sBl_u + off);
                b_l[2 * p][0] = r[0];
                b_l[2 * p][1] = r[1];
                b_l[2 * p + 1][0] = r[2];
                b_l[2 * p + 1][1] = r[3];
            }
#pragma unroll
            for (int mt = 0; mt < 2; ++mt) {
#pragma unroll
                for (int nt = 0; nt < 8; ++nt) {
                    mma_bf16(acc[mt][nt], a_h[mt], b_h[nt]);
                    mma_bf16(acc[mt][nt], a_l[mt], b_h[nt]);
                    mma_bf16(acc[mt][nt], a_h[mt], b_l[nt]);
                }
            }
        }
    }

#pragma unroll
    for (int mt = 0; mt < 2; ++mt) {
#pragma unroll
        for (int nt = 0; nt < 8; ++nt) {
            int r = cRow + warp_m * 32 + mt * 16 + (lane >> 2);
            int c = cCol + warp_n * 64 + nt * 8 + (lane & 3) * 2;
            *(float2*)&C[(size_t)r * N + c] = make_float2(acc[mt][nt][0], acc[mt][nt][1]);
            *(float2*)&C[(size_t)(r + 8) * N + c] = make_float2(acc[mt][nt][2], acc[mt][nt][3]);
        }
    }
}

// ------------- feature kernel -------------
__global__ void feat_kernel() {
    const int wg = (blockIdx.x * blockDim.x + threadIdx.x) >> 5;
    const int lane = threadIdx.x & 31;
    if (wg < TOK * H_) {
        const float* src = g_q + (size_t)wg * 64;
        float x0 = src[lane];
        float x1 = src[lane + 32];
        float m = fmaxf(x0, x1);
#pragma unroll
        for (int o = 16; o; o >>= 1) m = fmaxf(m, __shfl_xor_sync(0xffffffffu, m, o));
        float e0 = __expf(x0 - m);
        float e1 = __expf(x1 - m);
        float s = e0 + e1;
#pragma unroll
        for (int o = 16; o; o >>= 1) s += __shfl_xor_sync(0xffffffffu, s, o);
        float inv = 1.f / s;
        float* dst = g_ql + (size_t)wg * 64;
        dst[lane] = e0 * inv;
        dst[lane + 32] = e1 * inv;
    } else if (wg < TOK * H_ + TOK * HKV) {
        const int r = wg - TOK * H_;
        const float* src = g_k + (size_t)r * 64;
        float x0 = src[lane];
        float x1 = src[lane + 32];
        float m = fmaxf(x0, x1);
#pragma unroll
        for (int o = 16; o; o >>= 1) m = fmaxf(m, __shfl_xor_sync(0xffffffffu, m, o));
        float e0 = __expf(x0 - m);
        float e1 = __expf(x1 - m);
        float s = e0 + e1;
#pragma unroll
        for (int o = 16; o; o >>= 1) s += __shfl_xor_sync(0xffffffffu, s, o);
        float inv = 1.f / s;
        float* dst = g_kl + (size_t)r * 64;
        dst[lane] = e0 * inv;
        dst[lane + 32] = e1 * inv;
        float b0 = (fminf(x0, 0.f) - log1pf(__expf(-fabsf(x0)))) * 0.0625f;
        float b1 = (fminf(x1, 0.f) - log1pf(__expf(-fabsf(x1)))) * 0.0625f;
        float* bd = g_beta + (size_t)r * 64;
        bd[lane] = b0;
        bd[lane + 32] = b1;
    }
}

// --------- delta stage 1: per-(b,h,chunk) triangular solve (grid = 1024) ---------
__global__ void delta_stage1() {
    extern __shared__ float sm[];
    float* Kc = sm;
    float* W = Kc + 64 * PAD;
    float* U = W + 64 * PAD;
    float* L = U + 64 * PAD;
    float* Q = L + 64 * PAD;

    const int tid = threadIdx.x;
    const int blk = blockIdx.x;
    const int bh = blk >> 4;
    const int ch = blk & 15;
    const int b = bh >> 5;
    const int h = bh & 31;
    const int hkv = h >> 2;
    const int e = tid & 63;
    const int r0 = (tid >> 6) * 8;
    const int n0 = ch * CHUNK;

    for (int idx = tid; idx < 4096; idx += 512) {
        int c = idx >> 6;
        int d = idx & 63;
        int t = b * N_ + n0 + c;
        float kv = g_kl[(size_t)t * KDIM + hkv * 64 + d];
        float bt = g_beta[(size_t)t * KDIM + hkv * 64 + d];
        float vv = g_v[(size_t)t * KDIM + hkv * 64 + d];
        Kc[c * PAD + d] = kv;
        W[c * PAD + d] = kv * bt;
        U[c * PAD + d] = vv * bt;
        Q[c * PAD + d] = g_ql[(size_t)t * QDIM + h * 64 + d];
    }
    __syncthreads();

    {
        float acc[8];
#pragma unroll
        for (int i = 0; i < 8; ++i) acc[i] = 0.f;
        for (int d = 0; d < 64; ++d) {
            float kb = Kc[e * PAD + d];
#pragma unroll
            for (int i = 0; i < 8; ++i) acc[i] += W[(r0 + i) * PAD + d] * kb;
        }
#pragma unroll
        for (int i = 0; i < 8; ++i) {
            L[(r0 + i) * PAD + e] = (e < r0 + i) ? acc[i] : 0.f;
        }
    }
    __syncthreads();

    for (int j = 0; j < 63; ++j) {
        float uj = U[j * PAD + e];
        float wj = W[j * PAD + e];
        for (int i = j + 1 + (tid >> 6); i < 64; i += 8) {
            float lij = L[i * PAD + j];
            U[i * PAD + e] -= lij * uj;
            W[i * PAD + e] -= lij * wj;
        }
        __syncthreads();
    }

    {
        float acc[8];
#pragma unroll
        for (int i = 0; i < 8; ++i) acc[i] = 0.f;
        for (int d = 0; d < 64; ++d) {
            float kb = Kc[e * PAD + d];
#pragma unroll
            for (int i = 0; i < 8; ++i) acc[i] += Q[(r0 + i) * PAD + d] * kb;
        }
        float* Ao = g_A + (size_t)blk * 4096;
#pragma unroll
        for (int i = 0; i < 8; ++i) {
            Ao[(r0 + i) * 64 + e] = (e <= r0 + i) ? acc[i] : 0.f;
        }
    }
    {
        float* Wo_ = g_W + (size_t)blk * 4096;
        float* Uo_ = g_U + (size_t)blk * 4096;
#pragma unroll
        for (int i = 0; i < 8; ++i) {
            Wo_[(r0 + i) * 64 + e] = W[(r0 + i) * PAD + e];
            Uo_[(r0 + i) * 64 + e] = U[(r0 + i) * PAD + e];
        }
    }
}

// --------- delta stage 2: sequential scan over chunks, per (b,h) (grid = 64) -----
__global__ void delta_stage2() {
    extern __shared__ float sm[];
    float* S = sm;
    float* W = S + 64 * PAD;
    float* U = W + 64 * PAD;
    float* A = U + 64 * PAD;
    float* Q = A + 64 * PAD;
    float* Kc = Q + 64 * PAD;

    const int tid = threadIdx.x;
    const int bh = blockIdx.x;
    const int b = bh >> 5;
    const int h = bh & 31;
    const int hkv = h >> 2;
    const int e = tid & 63;
    const int r0 = (tid >> 6) * 8;

    for (int idx = tid; idx < 4096; idx += 512) {
        S[(idx >> 6) * PAD + (idx & 63)] = 0.f;
    }
    __syncthreads();

    for (int ch = 0; ch < NC; ++ch) {
        const int n0 = ch * CHUNK;
        const size_t base = (size_t)(bh * NC + ch) * 4096;
        for (int idx = tid; idx < 4096; idx += 512) {
            int c = idx >> 6;
            int d = idx & 63;
            int t = b * N_ + n0 + c;
            W[c * PAD + d] = g_W[base + idx];
            U[c * PAD + d] = g_U[base + idx];
            A[c * PAD + d] = g_A[base + idx];
            Q[c * PAD + d] = g_ql[(size_t)t * QDIM + h * 64 + d];
            Kc[c * PAD + d] = g_kl[(size_t)t * KDIM + hkv * 64 + d];
        }
        __syncthreads();

        {
            float acc[8];
#pragma unroll
            for (int i = 0; i < 8; ++i) acc[i] = 0.f;
            for (int d = 0; d < 64; ++d) {
                float s = S[d * PAD + e];
#pragma unroll
                for (int i = 0; i < 8; ++i) acc[i] += W[(r0 + i) * PAD + d] * s;
            }
#pragma unroll
            for (int i = 0; i < 8; ++i) U[(r0 + i) * PAD + e] -= acc[i];
        }
        __syncthreads();

        {
            float acc[8];
#pragma unroll
            for (int i = 0; i < 8; ++i) acc[i] = 0.f;
            for (int d = 0; d < 64; ++d) {
                float s = S[d * PAD + e];
#pragma unroll
                for (int i = 0; i < 8; ++i) acc[i] += Q[(r0 + i) * PAD + d] * s;
            }
            for (int j = 0; j < 64; ++j) {
                float u = U[j * PAD + e];
#pragma unroll
                for (int i = 0; i < 8; ++i) acc[i] += A[(r0 + i) * PAD + j] * u;
            }
#pragma unroll
            for (int i = 0; i < 8; ++i) {
                g_olin[(size_t)(b * N_ + n0 + r0 + i) * QDIM + h * 64 + e] = acc[i];
            }
        }
        __syncthreads();

        {
            float acc[8];
#pragma unroll
            for (int i = 0; i < 8; ++i) acc[i] = 0.f;
            for (int c = 0; c < 64; ++c) {
                float u = U[c * PAD + e];
#pragma unroll
                for (int i = 0; i < 8; ++i) acc[i] += Kc[c * PAD + r0 + i] * u;
            }
#pragma unroll
            for (int i = 0; i < 8; ++i) S[(r0 + i) * PAD + e] += acc[i];
        }
        __syncthreads();
    }
}

// --------------- base causal attention: block per (row i, head bh) ---------------
__global__ void base_attn_kernel(float* __restrict__ attnw) {
    __shared__ float sc[N_];
    __shared__ float qrow[64];
    __shared__ float sred[256];
    const int i = blockIdx.x;
    const int bh = blockIdx.y;
    const int b = bh >> 5;
    const int h = bh & 31;
    const int hkv = h >> 2;
    const int tid = threadIdx.x;
    const int lane = tid & 31;
    const int wrp = tid >> 5;
    const int ti = b * N_ + i;

    if (tid < 64) qrow[tid] = g_q[(size_t)ti * QDIM + h * 64 + tid];
    __syncthreads();

    const float scale = 0.125f;
    for (int j = wrp; j <= i; j += 8) {
        const float* kr = g_k + (size_t)(b * N_ + j) * KDIM + hkv * 64;
        float p = qrow[lane] * kr[lane] + qrow[lane + 32] * kr[lane + 32];
#pragma unroll
        for (int o = 16; o; o >>= 1) p += __shfl_xor_sync(0xffffffffu, p, o);
        if (lane == 0) sc[j] = p * scale;
    }
    __syncthreads();

    float m = -1e30f;
    for (int j = tid; j <= i; j += 256) m = fmaxf(m, sc[j]);
    sred[tid] = m;
    __syncthreads();
    for (int s = 128; s; s >>= 1) {
        if (tid < s) sred[tid] = fmaxf(sred[tid], sred[tid + s]);
        __syncthreads();
    }
    m = sred[0];
    __syncthreads();

    float lsum = 0.f;
    for (int j = tid; j <= i; j += 256) {
        float ev = __expf(sc[j] - m);
        sc[j] = ev;
        lsum += ev;
    }
    sred[tid] = lsum;
    __syncthreads();
    for (int s = 128; s; s >>= 1) {
        if (tid < s) sred[tid] += sred[tid + s];
        __syncthreads();
    }
    float inv = 1.f / sred[0];
    __syncthreads();
    for (int j = tid; j <= i; j += 256) sc[j] *= inv;
    __syncthreads();

    if (attnw) {
        float* arow = attnw + ((size_t)bh * N_ + i) * N_;
        for (int j = tid; j < N_; j += 256) arow[j] = (j <= i) ? sc[j] : 0.f;
    }

    const int d = tid & 63;
    const int part = tid >> 6;
    float acc = 0.f;
    for (int j = part; j <= i; j += 4) {
        acc += sc[j] * g_v[(size_t)(b * N_ + j) * KDIM + hkv * 64 + d];
    }
    sred[tid] = acc;
    __syncthreads();
    if (tid < 64) {
        float o = sred[tid] + sred[tid + 64] + sred[tid + 128] + sred[tid + 192];
        float mix = 0.5f * o + 0.5f * g_olin[(size_t)ti * QDIM + h * 64 + tid];
        g_omix[(size_t)ti * QDIM + h * 64 + tid] = mix;
    }
}

// ------------------------------------ launch -------------------------------------
extern "C" void kernel_launch(void* const* d_in, const int* in_sizes, int n_in,
                              void* d_out, int out_size) {
    const float* hs = (const float*)d_in[0];
    const float* Wq = (const float*)d_in[1];
    const float* Wk = (const float*)d_in[2];
    const float* Wv = (const float*)d_in[3];
    const float* Wo = (const float*)d_in[4];
    float* out = (float*)d_out;

    const size_t out_elems = (size_t)TOK * QDIM;
    const size_t attn_elems = (size_t)B_ * H_ * N_ * N_;
    float* attnw = ((size_t)out_size >= out_elems + attn_elems) ? (out + out_elems)
                                                                : (float*)0;

    float* qp;
    float* kp;
    float* vp;
    float* oxp;
    bf16* hshp; bf16* hslp;
    bf16* wqhp; bf16* wqlp;
    bf16* wkhp; bf16* wklp;
    bf16* wvhp; bf16* wvlp;
    bf16* wohp; bf16* wolp;
    bf16* oxhp; bf16* oxlp;
    cudaGetSymbolAddress((void**)&qp, g_q);
    cudaGetSymbolAddress((void**)&kp, g_k);
    cudaGetSymbolAddress((void**)&vp, g_v);
    cudaGetSymbolAddress((void**)&oxp, g_omix);
    cudaGetSymbolAddress((void**)&hshp, g_hsh);
    cudaGetSymbolAddress((void**)&hslp, g_hsl);
    cudaGetSymbolAddress((void**)&wqhp, g_wqh);
    cudaGetSymbolAddress((void**)&wqlp, g_wql);
    cudaGetSymbolAddress((void**)&wkhp, g_wkh);
    cudaGetSymbolAddress((void**)&wklp, g_wkl);
    cudaGetSymbolAddress((void**)&wvhp, g_wvh);
    cudaGetSymbolAddress((void**)&wvlp, g_wvl);
    cudaGetSymbolAddress((void**)&wohp, g_woh);
    cudaGetSymbolAddress((void**)&wolp, g_wol);
    cudaGetSymbolAddress((void**)&oxhp, g_oxh);
    cudaGetSymbolAddress((void**)&oxlp, g_oxl);

    split_kernel<<<(TOK * HID + 255) / 256, 256>>>(hs, hshp, hslp, TOK * HID);
    split_kernel<<<(HID * QDIM + 255) / 256, 256>>>(Wq, wqhp, wqlp, HID * QDIM);
    split_kernel<<<(HID * KDIM + 255) / 256, 256>>>(Wk, wkhp, wklp, HID * KDIM);
    split_kernel<<<(HID * KDIM + 255) / 256, 256>>>(Wv, wvhp, wvlp, HID * KDIM);
    split_kernel<<<(QDIM * HID + 255) / 256, 256>>>(Wo, wohp, wolp, QDIM * HID);

    bgemm<<<dim3(QDIM / 128, TOK / 128), 256>>>(hshp, hslp, wqhp, wqlp, qp, QDIM, HID);
    bgemm<<<dim3(KDIM / 128, TOK / 128), 256>>>(hshp, hslp, wkhp, wklp, kp, KDIM, HID);
    bgemm<<<dim3(KDIM / 128, TOK / 128), 256>>>(hshp, hslp, wvhp, wvlp, vp, KDIM, HID);

    {
        const int total_warps = TOK * H_ + TOK * HKV;
        const int blocks = (total_warps * 32 + 255) / 256;
        feat_kernel<<<blocks, 256>>>();
    }

    cudaFuncSetAttribute(delta_stage1, cudaFuncAttributeMaxDynamicSharedMemorySize,
                         5 * 64 * PAD * (int)sizeof(float));
    delta_stage1<<<B_ * H_ * NC, 512, 5 * 64 * PAD * sizeof(float)>>>();
    cudaFuncSetAttribute(delta_stage2, cudaFuncAttributeMaxDynamicSharedMemorySize,
                         6 * 64 * PAD * (int)sizeof(float));
    delta_stage2<<<B_ * H_, 512, 6 * 64 * PAD * sizeof(float)>>>();

    base_attn_kernel<<<dim3(N_, B_ * H_), 256>>>(attnw);

    split_kernel<<<(TOK * QDIM + 255) / 256, 256>>>(oxp, oxhp, oxlp, TOK * QDIM);
    bgemm<<<dim3(QDIM / 128, TOK / 128), 256>>>(oxhp, oxlp, wohp, wolp, out, QDIM, HID);
}

// round 6
// speedup vs baseline: 2.7799x; 1.9875x over previous
#include <cuda_runtime.h>
#include <cuda_bf16.h>
#include <math.h>
#include <stdint.h>

typedef __nv_bfloat16 bf16;
typedef unsigned int u32;

#define B_    2
#define N_    1024
#define HID   2048
#define H_    32
#define D_    64
#define HKV   8
#define CHUNK 64
#define NC    16
#define TOK   (B_ * N_)
#define QDIM  (H_ * D_)
#define KDIM  (HKV * D_)
#define KVD   1024          // fused k|v row stride
#define PAD   65

// ---------------- fp32 scratch ----------------
__device__ float g_q[TOK * QDIM];
__device__ float g_kv[TOK * KVD];        // [t][0:512)=k, [512:1024)=v
__device__ float g_ql[TOK * QDIM];
__device__ float g_kl[TOK * KDIM];
__device__ float g_beta[TOK * KDIM];
__device__ float g_olin[TOK * QDIM];
__device__ float g_obase[TOK * QDIM];
__device__ float g_W[B_ * H_ * NC * 64 * 64];
__device__ float g_U[B_ * H_ * NC * 64 * 64];
__device__ float g_A[B_ * H_ * NC * 64 * 64];
// bf16 split scratch
__device__ bf16 g_hsh[TOK * HID];
__device__ bf16 g_hsl[TOK * HID];
__device__ bf16 g_wqh[HID * QDIM];
__device__ bf16 g_wql[HID * QDIM];
__device__ bf16 g_wkvh[HID * KVD];
__device__ bf16 g_wkvl[HID * KVD];
__device__ bf16 g_woh[QDIM * HID];
__device__ bf16 g_wol[QDIM * HID];
__device__ bf16 g_oxh[TOK * QDIM];
__device__ bf16 g_oxl[TOK * QDIM];

// ---------------- fused split: hs, Wq, Wk, Wv, Wo -> bf16 hi/lo ----------------
#define SEG0 (TOK * HID)          // hs      4M
#define SEG1 (HID * QDIM)         // Wq      4M
#define SEG2 (HID * KDIM)         // Wk      2M
#define SEG3 (HID * KDIM)         // Wv      2M
#define SEG4 (QDIM * HID)         // Wo      4M
__global__ void split_all(const float* __restrict__ hs, const float* __restrict__ Wq,
                          const float* __restrict__ Wk, const float* __restrict__ Wv,
                          const float* __restrict__ Wo) {
    int i = blockIdx.x * 256 + threadIdx.x;
    float x;
    bf16* hp;
    bf16* lp;
    size_t dst;
    if (i < SEG0) {
        x = hs[i]; hp = g_hsh; lp = g_hsl; dst = i;
    } else if (i < SEG0 + SEG1) {
        int j = i - SEG0;
        x = Wq[j]; hp = g_wqh; lp = g_wql; dst = j;
    } else if (i < SEG0 + SEG1 + SEG2) {
        int j = i - SEG0 - SEG1;
        int r = j >> 9, c = j & 511;
        x = Wk[j]; hp = g_wkvh; lp = g_wkvl; dst = (size_t)r * KVD + c;
    } else if (i < SEG0 + SEG1 + SEG2 + SEG3) {
        int j = i - SEG0 - SEG1 - SEG2;
        int r = j >> 9, c = j & 511;
        x = Wv[j]; hp = g_wkvh; lp = g_wkvl; dst = (size_t)r * KVD + 512 + c;
    } else if (i < SEG0 + SEG1 + SEG2 + SEG3 + SEG4) {
        int j = i - SEG0 - SEG1 - SEG2 - SEG3;
        x = Wo[j]; hp = g_woh; lp = g_wol; dst = j;
    } else {
        return;
    }
    bf16 hv = __float2bfloat16(x);
    hp[dst] = hv;
    lp[dst] = __float2bfloat16(x - __bfloat162float(hv));
}

// ---------------- mma wrappers ----------------
__device__ __forceinline__ void ldsm_x4(u32* r, u32 addr) {
    asm volatile("ldmatrix.sync.aligned.m8n8.x4.shared.b16 {%0,%1,%2,%3}, [%4];"
                 : "=r"(r[0]), "=r"(r[1]), "=r"(r[2]), "=r"(r[3]) : "r"(addr));
}
__device__ __forceinline__ void ldsm_x4t(u32* r, u32 addr) {
    asm volatile("ldmatrix.sync.aligned.m8n8.x4.trans.shared.b16 {%0,%1,%2,%3}, [%4];"
                 : "=r"(r[0]), "=r"(r[1]), "=r"(r[2]), "=r"(r[3]) : "r"(addr));
}
__device__ __forceinline__ void mma_bf16(float* c, const u32* a, const u32* b) {
    asm volatile(
        "mma.sync.aligned.m16n8k16.row.col.f32.bf16.bf16.f32 "
        "{%0,%1,%2,%3}, {%4,%5,%6,%7}, {%8,%9}, {%0,%1,%2,%3};"
        : "+f"(c[0]), "+f"(c[1]), "+f"(c[2]), "+f"(c[3])
        : "r"(a[0]), "r"(a[1]), "r"(a[2]), "r"(a[3]), "r"(b[0]), "r"(b[1]));
}

// C[M,N] ~= AhBh + AlBh + AhBl, fp32 out. 128x128 tile, BK=32, 256 thr (4x2 warps).
#define ASTRIDE 40
#define BSTRIDE 136
__global__ void bgemm(const bf16* __restrict__ Ah, const bf16* __restrict__ Al,
                      const bf16* __restrict__ Bh, const bf16* __restrict__ Bl,
                      float* __restrict__ C, int N, int K) {
    __shared__ bf16 sAh[128 * ASTRIDE];
    __shared__ bf16 sAl[128 * ASTRIDE];
    __shared__ bf16 sBh[32 * BSTRIDE];
    __shared__ bf16 sBl[32 * BSTRIDE];

    const int tid = threadIdx.x;
    const int lane = tid & 31;
    const int wid = tid >> 5;
    const int warp_m = wid & 3;
    const int warp_n = wid >> 2;
    const int cRow = blockIdx.y * 128;
    const int cCol = blockIdx.x * 128;

    const int aRow = tid >> 1;
    const int aKc = (tid & 1) * 16;
    const int bK = tid >> 3;
    const int bNc = (tid & 7) * 16;
    const bf16* ApH = Ah + (size_t)(cRow + aRow) * K + aKc;
    const bf16* ApL = Al + (size_t)(cRow + aRow) * K + aKc;
    const bf16* BpH = Bh + (size_t)bK * N + cCol + bNc;
    const bf16* BpL = Bl + (size_t)bK * N + cCol + bNc;

    u32 sAh_u = (u32)__cvta_generic_to_shared(sAh);
    u32 sAl_u = (u32)__cvta_generic_to_shared(sAl);
    u32 sBh_u = (u32)__cvta_generic_to_shared(sBh);
    u32 sBl_u = (u32)__cvta_generic_to_shared(sBl);

    float acc[2][8][4];
#pragma unroll
    for (int mt = 0; mt < 2; ++mt) {
#pragma unroll
        for (int nt = 0; nt < 8; ++nt) {
#pragma unroll
            for (int i = 0; i < 4; ++i) acc[mt][nt][i] = 0.f;
        }
    }

    const int T = K >> 5;
    for (int kt = 0; kt < T; ++kt) {
        uint4 ah0 = *(const uint4*)(ApH + (size_t)kt * 32);
        uint4 ah1 = *(const uint4*)(ApH + (size_t)kt * 32 + 8);
        uint4 al0 = *(const uint4*)(ApL + (size_t)kt * 32);
        uint4 al1 = *(const uint4*)(ApL + (size_t)kt * 32 + 8);
        uint4 bh0 = *(const uint4*)(BpH + (size_t)kt * 32 * N);
        uint4 bh1 = *(const uint4*)(BpH + (size_t)kt * 32 * N + 8);
        uint4 bl0 = *(const uint4*)(BpL + (size_t)kt * 32 * N);
        uint4 bl1 = *(const uint4*)(BpL + (size_t)kt * 32 * N + 8);
        __syncthreads();
        *(uint4*)(sAh + aRow * ASTRIDE + aKc)     = ah0;
        *(uint4*)(sAh + aRow * ASTRIDE + aKc + 8) = ah1;
        *(uint4*)(sAl + aRow * ASTRIDE + aKc)     = al0;
        *(uint4*)(sAl + aRow * ASTRIDE + aKc + 8) = al1;
        *(uint4*)(sBh + bK * BSTRIDE + bNc)       = bh0;
        *(uint4*)(sBh + bK * BSTRIDE + bNc + 8)   = bh1;
        *(uint4*)(sBl + bK * BSTRIDE + bNc)       = bl0;
        *(uint4*)(sBl + bK * BSTRIDE + bNc + 8)   = bl1;
        __syncthreads();

#pragma unroll
        for (int kk = 0; kk < 32; kk += 16) {
            u32 a_h[2][4];
            u32 a_l[2][4];
            u32 b_h[8][2];
            u32 b_l[8][2];
#pragma unroll
            for (int mt = 0; mt < 2; ++mt) {
                int row = warp_m * 32 + mt * 16 + (lane & 15);
                u32 off = (u32)((row * ASTRIDE + kk + (lane >> 4) * 8) * 2);
                ldsm_x4(a_h[mt], sAh_u + off);
                ldsm_x4(a_l[mt], sAl_u + off);
            }
#pragma unroll
            for (int p = 0; p < 4; ++p) {
                int colbase = warp_n * 64 + p * 16;
                int krow = kk + (lane & 7) + ((lane >> 3) & 1) * 8;
                int col = colbase + ((lane >> 4) & 1) * 8;
                u32 off = (u32)((krow * BSTRIDE + col) * 2);
                u32 r[4];
                ldsm_x4t(r, sBh_u + off);
                b_h[2 * p][0] = r[0];
                b_h[2 * p][1] = r[1];
                b_h[2 * p + 1][0] = r[2];
                b_h[2 * p + 1][1] = r[3];
                ldsm_x4t(r, sBl_u + off);
                b_l[2 * p][0] = r[0];
                b_l[2 * p][1] = r[1];
                b_l[2 * p + 1][0] = r[2];
                b_l[2 * p + 1][1] = r[3];
            }
#pragma unroll
            for (int mt = 0; mt < 2; ++mt) {
#pragma unroll
                for (int nt = 0; nt < 8; ++nt) {
                    mma_bf16(acc[mt][nt], a_h[mt], b_h[nt]);
                    mma_bf16(acc[mt][nt], a_l[mt], b_h[nt]);
                    mma_bf16(acc[mt][nt], a_h[mt], b_l[nt]);
                }
            }
        }
    }

#pragma unroll
    for (int mt = 0; mt < 2; ++mt) {
#pragma unroll
        for (int nt = 0; nt < 8; ++nt) {
            int r = cRow + warp_m * 32 + mt * 16 + (lane >> 2);
            int c = cCol + warp_n * 64 + nt * 8 + (lane & 3) * 2;
            *(float2*)&C[(size_t)r * N + c] = make_float2(acc[mt][nt][0], acc[mt][nt][1]);
            *(float2*)&C[(size_t)(r + 8) * N + c] = make_float2(acc[mt][nt][2], acc[mt][nt][3]);
        }
    }
}

// ------------- feature kernel -------------
__global__ void feat_kernel() {
    const int wg = (blockIdx.x * blockDim.x + threadIdx.x) >> 5;
    const int lane = threadIdx.x & 31;
    if (wg < TOK * H_) {
        const float* src = g_q + (size_t)wg * 64;
        float x0 = src[lane];
        float x1 = src[lane + 32];
        float m = fmaxf(x0, x1);
#pragma unroll
        for (int o = 16; o; o >>= 1) m = fmaxf(m, __shfl_xor_sync(0xffffffffu, m, o));
        float e0 = __expf(x0 - m);
        float e1 = __expf(x1 - m);
        float s = e0 + e1;
#pragma unroll
        for (int o = 16; o; o >>= 1) s += __shfl_xor_sync(0xffffffffu, s, o);
        float inv = 1.f / s;
        float* dst = g_ql + (size_t)wg * 64;
        dst[lane] = e0 * inv;
        dst[lane + 32] = e1 * inv;
    } else if (wg < TOK * H_ + TOK * HKV) {
        const int r = wg - TOK * H_;
        const float* src = g_kv + (size_t)(r >> 3) * KVD + (r & 7) * 64;
        float x0 = src[lane];
        float x1 = src[lane + 32];
        float m = fmaxf(x0, x1);
#pragma unroll
        for (int o = 16; o; o >>= 1) m = fmaxf(m, __shfl_xor_sync(0xffffffffu, m, o));
        float e0 = __expf(x0 - m);
        float e1 = __expf(x1 - m);
        float s = e0 + e1;
#pragma unroll
        for (int o = 16; o; o >>= 1) s += __shfl_xor_sync(0xffffffffu, s, o);
        float inv = 1.f / s;
        float* dst = g_kl + (size_t)r * 64;
        dst[lane] = e0 * inv;
        dst[lane + 32] = e1 * inv;
        float b0 = (fminf(x0, 0.f) - log1pf(__expf(-fabsf(x0)))) * 0.0625f;
        float b1 = (fminf(x1, 0.f) - log1pf(__expf(-fabsf(x1)))) * 0.0625f;
        float* bd = g_beta + (size_t)r * 64;
        bd[lane] = b0;
        bd[lane + 32] = b1;
    }
}

// --------- delta stage 1: per-(b,h,chunk) triangular solve (grid = 1024) ---------
__global__ void delta_stage1() {
    extern __shared__ float sm[];
    float* Kc = sm;
    float* W = Kc + 64 * PAD;
    float* U = W + 64 * PAD;
    float* L = U + 64 * PAD;
    float* Q = L + 64 * PAD;

    const int tid = threadIdx.x;
    const int blk = blockIdx.x;
    const int bh = blk >> 4;
    const int ch = blk & 15;
    const int b = bh >> 5;
    const int h = bh & 31;
    const int hkv = h >> 2;
    const int e = tid & 63;
    const int r0 = (tid >> 6) * 8;
    const int n0 = ch * CHUNK;

    for (int idx = tid; idx < 4096; idx += 512) {
        int c = idx >> 6;
        int d = idx & 63;
        int t = b * N_ + n0 + c;
        float kv = g_kl[(size_t)t * KDIM + hkv * 64 + d];
        float bt = g_beta[(size_t)t * KDIM + hkv * 64 + d];
        float vv = g_kv[(size_t)t * KVD + 512 + hkv * 64 + d];
        Kc[c * PAD + d] = kv;
        W[c * PAD + d] = kv * bt;
        U[c * PAD + d] = vv * bt;
        Q[c * PAD + d] = g_ql[(size_t)t * QDIM + h * 64 + d];
    }
    __syncthreads();

    {
        float acc[8];
#pragma unroll
        for (int i = 0; i < 8; ++i) acc[i] = 0.f;
        for (int d = 0; d < 64; ++d) {
            float kb = Kc[e * PAD + d];
#pragma unroll
            for (int i = 0; i < 8; ++i) acc[i] += W[(r0 + i) * PAD + d] * kb;
        }
#pragma unroll
        for (int i = 0; i < 8; ++i) {
            L[(r0 + i) * PAD + e] = (e < r0 + i) ? acc[i] : 0.f;
        }
    }
    __syncthreads();

    for (int j = 0; j < 63; ++j) {
        float uj = U[j * PAD + e];
        float wj = W[j * PAD + e];
        for (int i = j + 1 + (tid >> 6); i < 64; i += 8) {
            float lij = L[i * PAD + j];
            U[i * PAD + e] -= lij * uj;
            W[i * PAD + e] -= lij * wj;
        }
        __syncthreads();
    }

    {
        float acc[8];
#pragma unroll
        for (int i = 0; i < 8; ++i) acc[i] = 0.f;
        for (int d = 0; d < 64; ++d) {
            float kb = Kc[e * PAD + d];
#pragma unroll
            for (int i = 0; i < 8; ++i) acc[i] += Q[(r0 + i) * PAD + d] * kb;
        }
        float* Ao = g_A + (size_t)blk * 4096;
#pragma unroll
        for (int i = 0; i < 8; ++i) {
            Ao[(r0 + i) * 64 + e] = (e <= r0 + i) ? acc[i] : 0.f;
        }
    }
    {
        float* Wo_ = g_W + (size_t)blk * 4096;
        float* Uo_ = g_U + (size_t)blk * 4096;
#pragma unroll
        for (int i = 0; i < 8; ++i) {
            Wo_[(r0 + i) * 64 + e] = W[(r0 + i) * PAD + e];
            Uo_[(r0 + i) * 64 + e] = U[(r0 + i) * PAD + e];
        }
    }
}

// --------------- tiled base causal attention: block per (i-tile, bh) -------------
// writes unnormalized exp to attnw, renormalizes in place; o_base -> g_obase
__global__ void base_attn_tiled(float* __restrict__ attnw) {
    extern __shared__ float sm[];
    float* Qt = sm;                 // 64 x PAD
    float* Kt = Qt + 64 * PAD;
    float* Vt = Kt + 64 * PAD;
    float* Et = Vt + 64 * PAD;

    const int it = blockIdx.x;      // 0..15
    const int bh = blockIdx.y;      // 0..63
    const int b = bh >> 5;
    const int h = bh & 31;
    const int hkv = h >> 2;
    const int tid = threadIdx.x;    // 256
    const int ty = tid >> 4;
    const int tx = tid & 15;

    for (int idx = tid; idx < 4096; idx += 256) {
        int r = idx >> 6;
        int d = idx & 63;
        Qt[r * PAD + d] = g_q[(size_t)(b * N_ + it * 64 + r) * QDIM + h * 64 + d] * 0.125f;
    }

    float o[4][4];
    float rs[4];
#pragma unroll
    for (int i = 0; i < 4; ++i) {
        rs[i] = 0.f;
#pragma unroll
        for (int j = 0; j < 4; ++j) o[i][j] = 0.f;
    }

    for (int jt = 0; jt <= it; ++jt) {
        __syncthreads();
        for (int idx = tid; idx < 4096; idx += 256) {
            int r = idx >> 6;
            int d = idx & 63;
            const float* kvrow = g_kv + (size_t)(b * N_ + jt * 64 + r) * KVD + hkv * 64;
            Kt[r * PAD + d] = kvrow[d];
            Vt[r * PAD + d] = kvrow[512 + d];
        }
        __syncthreads();

        float s[4][4];
#pragma unroll
        for (int i = 0; i < 4; ++i) {
#pragma unroll
            for (int j = 0; j < 4; ++j) s[i][j] = 0.f;
        }
        for (int d = 0; d < 64; ++d) {
            float qv[4];
            float kv[4];
#pragma unroll
            for (int i = 0; i < 4; ++i) qv[i] = Qt[(ty * 4 + i) * PAD + d];
#pragma unroll
            for (int j = 0; j < 4; ++j) kv[j] = Kt[(tx * 4 + j) * PAD + d];
#pragma unroll
            for (int i = 0; i < 4; ++i) {
#pragma unroll
                for (int j = 0; j < 4; ++j) s[i][j] += qv[i] * kv[j];
            }
        }
        // mask + exp; accumulate row sums; stash exp in s
#pragma unroll
        for (int i = 0; i < 4; ++i) {
            int gr = it * 64 + ty * 4 + i;
#pragma unroll
            for (int j = 0; j < 4; ++j) {
                int gc = jt * 64 + tx * 4 + j;
                float e = (gc <= gr) ? __expf(s[i][j]) : 0.f;
                s[i][j] = e;
                rs[i] += e;
                Et[(ty * 4 + i) * PAD + tx * 4 + j] = e;
            }
        }
        // write unnormalized exp tile
        if (attnw) {
#pragma unroll
            for (int i = 0; i < 4; ++i) {
                int gr = it * 64 + ty * 4 + i;
                float4 v4 = make_float4(s[i][0], s[i][1], s[i][2], s[i][3]);
                *(float4*)&attnw[((size_t)bh * N_ + gr) * N_ + jt * 64 + tx * 4] = v4;
            }
        }
        __syncthreads();
        // AV accumulate: o[r][d] += sum_c Et[r][c] * Vt[c][d]
        for (int c = 0; c < 64; ++c) {
            float ev[4];
            float vv[4];
#pragma unroll
            for (int i = 0; i < 4; ++i) ev[i] = Et[(ty * 4 + i) * PAD + c];
#pragma unroll
            for (int j = 0; j < 4; ++j) vv[j] = Vt[c * PAD + tx * 4 + j];
#pragma unroll
            for (int i = 0; i < 4; ++i) {
#pragma unroll
                for (int j = 0; j < 4; ++j) o[i][j] += ev[i] * vv[j];
            }
        }
    }

    // zero future (upper) tiles of attnw
    if (attnw) {
        float4 z4 = make_float4(0.f, 0.f, 0.f, 0.f);
        for (int jt = it + 1; jt < 16; ++jt) {
#pragma unroll
            for (int i = 0; i < 4; ++i) {
                int gr = it * 64 + ty * 4 + i;
                *(float4*)&attnw[((size_t)bh * N_ + gr) * N_ + jt * 64 + tx * 4] = z4;
            }
        }
    }

    // reduce row sums across the 16 tx lanes (xor 1,2,4,8 stays in 16-lane group)
#pragma unroll
    for (int i = 0; i < 4; ++i) {
#pragma unroll
        for (int off = 1; off < 16; off <<= 1) {
            rs[i] += __shfl_xor_sync(0xffffffffu, rs[i], off);
        }
    }
    float inv[4];
#pragma unroll
    for (int i = 0; i < 4; ++i) inv[i] = 1.f / rs[i];

    // write normalized o_base
#pragma unroll
    for (int i = 0; i < 4; ++i) {
        int gr = it * 64 + ty * 4 + i;
#pragma unroll
        for (int j = 0; j < 4; ++j) {
            g_obase[(size_t)(b * N_ + gr) * QDIM + h * 64 + tx * 4 + j] = o[i][j] * inv[i];
        }
    }

    // renormalize attnw (each thread re-reads exactly what it wrote)
    if (attnw) {
        for (int jt = 0; jt <= it; ++jt) {
#pragma unroll
            for (int i = 0; i < 4; ++i) {
                int gr = it * 64 + ty * 4 + i;
                float* p = &attnw[((size_t)bh * N_ + gr) * N_ + jt * 64 + tx * 4];
                float4 v4 = *(float4*)p;
                v4.x *= inv[i];
                v4.y *= inv[i];
                v4.z *= inv[i];
                v4.w *= inv[i];
                *(float4*)p = v4;
            }
        }
    }
}

// --------- delta stage 2: sequential scan over chunks, per (b,h) (grid = 64) -----
__global__ void delta_stage2() {
    extern __shared__ float sm[];
    float* S = sm;
    float* W = S + 64 * PAD;
    float* U = W + 64 * PAD;
    float* A = U + 64 * PAD;
    float* Q = A + 64 * PAD;
    float* Kc = Q + 64 * PAD;

    const int tid = threadIdx.x;
    const int bh = blockIdx.x;
    const int b = bh >> 5;
    const int h = bh & 31;
    const int hkv = h >> 2;
    const int e = tid & 63;
    const int r0 = (tid >> 6) * 8;

    for (int idx = tid; idx < 4096; idx += 512) {
        S[(idx >> 6) * PAD + (idx & 63)] = 0.f;
    }
    __syncthreads();

    for (int ch = 0; ch < NC; ++ch) {
        const int n0 = ch * CHUNK;
        const size_t base = (size_t)(bh * NC + ch) * 4096;
        for (int idx = tid; idx < 4096; idx += 512) {
            int c = idx >> 6;
            int d = idx & 63;
            int t = b * N_ + n0 + c;
            W[c * PAD + d] = g_W[base + idx];
            U[c * PAD + d] = g_U[base + idx];
            A[c * PAD + d] = g_A[base + idx];
            Q[c * PAD + d] = g_ql[(size_t)t * QDIM + h * 64 + d];
            Kc[c * PAD + d] = g_kl[(size_t)t * KDIM + hkv * 64 + d];
        }
        __syncthreads();

        {
            float acc[8];
#pragma unroll
            for (int i = 0; i < 8; ++i) acc[i] = 0.f;
            for (int d = 0; d < 64; ++d) {
                float s = S[d * PAD + e];
#pragma unroll
                for (int i = 0; i < 8; ++i) acc[i] += W[(r0 + i) * PAD + d] * s;
            }
#pragma unroll
            for (int i = 0; i < 8; ++i) U[(r0 + i) * PAD + e] -= acc[i];
        }
        __syncthreads();

        {
            float acc[8];
#pragma unroll
            for (int i = 0; i < 8; ++i) acc[i] = 0.f;
            for (int d = 0; d < 64; ++d) {
                float s = S[d * PAD + e];
#pragma unroll
                for (int i = 0; i < 8; ++i) acc[i] += Q[(r0 + i) * PAD + d] * s;
            }
            for (int j = 0; j < 64; ++j) {
                float u = U[j * PAD + e];
#pragma unroll
                for (int i = 0; i < 8; ++i) acc[i] += A[(r0 + i) * PAD + j] * u;
            }
#pragma unroll
            for (int i = 0; i < 8; ++i) {
                g_olin[(size_t)(b * N_ + n0 + r0 + i) * QDIM + h * 64 + e] = acc[i];
            }
        }
        __syncthreads();

        {
            float acc[8];
#pragma unroll
            for (int i = 0; i < 8; ++i) acc[i] = 0.f;
            for (int c = 0; c < 64; ++c) {
                float u = U[c * PAD + e];
#pragma unroll
                for (int i = 0; i < 8; ++i) acc[i] += Kc[c * PAD + r0 + i] * u;
            }
#pragma unroll
            for (int i = 0; i < 8; ++i) S[(r0 + i) * PAD + e] += acc[i];
        }
        __syncthreads();
    }
}

// --------- mix 0.5*o_lin + 0.5*o_base and split to bf16 hi/lo -------------------
__global__ void split_mix() {
    int i = blockIdx.x * 256 + threadIdx.x;
    if (i < TOK * QDIM) {
        float x = 0.5f * g_obase[i] + 0.5f * g_olin[i];
        bf16 hv = __float2bfloat16(x);
        g_oxh[i] = hv;
        g_oxl[i] = __float2bfloat16(x - __bfloat162float(hv));
    }
}

// ------------------------------------ launch -------------------------------------
extern "C" void kernel_launch(void* const* d_in, const int* in_sizes, int n_in,
                              void* d_out, int out_size) {
    const float* hs = (const float*)d_in[0];
    const float* Wq = (const float*)d_in[1];
    const float* Wk = (const float*)d_in[2];
    const float* Wv = (const float*)d_in[3];
    const float* Wo = (const float*)d_in[4];
    float* out = (float*)d_out;

    const size_t out_elems = (size_t)TOK * QDIM;
    const size_t attn_elems = (size_t)B_ * H_ * N_ * N_;
    float* attnw = ((size_t)out_size >= out_elems + attn_elems) ? (out + out_elems)
                                                                : (float*)0;

    float* qp;
    float* kvp;
    bf16* hshp; bf16* hslp;
    bf16* wqhp; bf16* wqlp;
    bf16* wkvhp; bf16* wkvlp;
    bf16* wohp; bf16* wolp;
    bf16* oxhp; bf16* oxlp;
    cudaGetSymbolAddress((void**)&qp, g_q);
    cudaGetSymbolAddress((void**)&kvp, g_kv);
    cudaGetSymbolAddress((void**)&hshp, g_hsh);
    cudaGetSymbolAddress((void**)&hslp, g_hsl);
    cudaGetSymbolAddress((void**)&wqhp, g_wqh);
    cudaGetSymbolAddress((void**)&wqlp, g_wql);
    cudaGetSymbolAddress((void**)&wkvhp, g_wkvh);
    cudaGetSymbolAddress((void**)&wkvlp, g_wkvl);
    cudaGetSymbolAddress((void**)&wohp, g_woh);
    cudaGetSymbolAddress((void**)&wolp, g_wol);
    cudaGetSymbolAddress((void**)&oxhp, g_oxh);
    cudaGetSymbolAddress((void**)&oxlp, g_oxl);

    // 1: fused split of all fp32 inputs
    {
        const int total = SEG0 + SEG1 + SEG2 + SEG3 + SEG4;
        split_all<<<(total + 255) / 256, 256>>>(hs, Wq, Wk, Wv, Wo);
    }

    // 2-3: projections (q; fused k|v)
    bgemm<<<dim3(QDIM / 128, TOK / 128), 256>>>(hshp, hslp, wqhp, wqlp, qp, QDIM, HID);
    bgemm<<<dim3(KVD / 128, TOK / 128), 256>>>(hshp, hslp, wkvhp, wkvlp, kvp, KVD, HID);

    // 4: feature maps + gate
    {
        const int total_warps = TOK * H_ + TOK * HKV;
        const int blocks = (total_warps * 32 + 255) / 256;
        feat_kernel<<<blocks, 256>>>();
    }

    // 5: delta stage 1 (parallel triangular solves)
    cudaFuncSetAttribute(delta_stage1, cudaFuncAttributeMaxDynamicSharedMemorySize,
                         5 * 64 * PAD * (int)sizeof(float));
    delta_stage1<<<B_ * H_ * NC, 512, 5 * 64 * PAD * sizeof(float)>>>();

    // 6: base attention (profiled slot)
    cudaFuncSetAttribute(base_attn_tiled, cudaFuncAttributeMaxDynamicSharedMemorySize,
                         4 * 64 * PAD * (int)sizeof(float));
    base_attn_tiled<<<dim3(16, B_ * H_), 256, 4 * 64 * PAD * sizeof(float)>>>(attnw);

    // 7: delta stage 2 (sequential scan)
    cudaFuncSetAttribute(delta_stage2, cudaFuncAttributeMaxDynamicSharedMemorySize,
                         6 * 64 * PAD * (int)sizeof(float));
    delta_stage2<<<B_ * H_, 512, 6 * 64 * PAD * sizeof(float)>>>();

    // 8: mix + split
    split_mix<<<(TOK * QDIM + 255) / 256, 256>>>();

    // 9: output projection
    bgemm<<<dim3(QDIM / 128, TOK / 128), 256>>>(oxhp, oxlp, wohp, wolp, out, QDIM, HID);
}

// round 8
// speedup vs baseline: 3.3740x; 1.2137x over previous
#include <cuda_runtime.h>
#include <cuda_fp16.h>
#include <math.h>
#include <stdint.h>

typedef unsigned int u32;

#define B_    2
#define N_    1024
#define HID   2048
#define H_    32
#define D_    64
#define HKV   8
#define CHUNK 64
#define NC    16
#define TOK   (B_ * N_)
#define QDIM  (H_ * D_)
#define KDIM  (HKV * D_)
#define KVD   1024
#define PAD   65

// ---------------- fp32 scratch ----------------
__device__ float g_q[TOK * QDIM];
__device__ float g_kv[TOK * KVD];        // [t][0:512)=k, [512:1024)=v
__device__ float g_ql[TOK * QDIM];
__device__ float g_kl[TOK * KDIM];
__device__ float g_beta[TOK * KDIM];
__device__ float g_olin[TOK * QDIM];
__device__ float g_obase[TOK * QDIM];
__device__ float g_W[B_ * H_ * NC * 64 * 64];
__device__ float g_U[B_ * H_ * NC * 64 * 64];
__device__ float g_A[B_ * H_ * NC * 64 * 64];
// fp16 scratch: activations split hi/lo, weights single
__device__ __half g_hsh[TOK * HID];
__device__ __half g_hsl[TOK * HID];
__device__ __half g_wq[HID * QDIM];
__device__ __half g_wkv[HID * KVD];
__device__ __half g_wo[QDIM * HID];
__device__ __half g_oxh[TOK * QDIM];
__device__ __half g_oxl[TOK * QDIM];

// ---------------- fused split/convert: hs (hi/lo), weights (single) --------------
#define SEG0 (TOK * HID)
#define SEG1 (HID * QDIM)
#define SEG2 (HID * KDIM)
#define SEG3 (HID * KDIM)
#define SEG4 (QDIM * HID)
__global__ void split_all(const float* __restrict__ hs, const float* __restrict__ Wq,
                          const float* __restrict__ Wk, const float* __restrict__ Wv,
                          const float* __restrict__ Wo) {
    int i = blockIdx.x * 256 + threadIdx.x;
    if (i < SEG0) {
        float x = hs[i];
        __half hv = __float2half(x);
        g_hsh[i] = hv;
        g_hsl[i] = __float2half(x - __half2float(hv));
    } else if (i < SEG0 + SEG1) {
        int j = i - SEG0;
        g_wq[j] = __float2half(Wq[j]);
    } else if (i < SEG0 + SEG1 + SEG2) {
        int j = i - SEG0 - SEG1;
        int r = j >> 9, c = j & 511;
        g_wkv[(size_t)r * KVD + c] = __float2half(Wk[j]);
    } else if (i < SEG0 + SEG1 + SEG2 + SEG3) {
        int j = i - SEG0 - SEG1 - SEG2;
        int r = j >> 9, c = j & 511;
        g_wkv[(size_t)r * KVD + 512 + c] = __float2half(Wv[j]);
    } else if (i < SEG0 + SEG1 + SEG2 + SEG3 + SEG4) {
        int j = i - SEG0 - SEG1 - SEG2 - SEG3;
        g_wo[j] = __float2half(Wo[j]);
    }
}

// ---------------- mma wrappers ----------------
__device__ __forceinline__ void ldsm_x4(u32* r, u32 addr) {
    asm volatile("ldmatrix.sync.aligned.m8n8.x4.shared.b16 {%0,%1,%2,%3}, [%4];"
                 : "=r"(r[0]), "=r"(r[1]), "=r"(r[2]), "=r"(r[3]) : "r"(addr));
}
__device__ __forceinline__ void ldsm_x4t(u32* r, u32 addr) {
    asm volatile("ldmatrix.sync.aligned.m8n8.x4.trans.shared.b16 {%0,%1,%2,%3}, [%4];"
                 : "=r"(r[0]), "=r"(r[1]), "=r"(r[2]), "=r"(r[3]) : "r"(addr));
}
__device__ __forceinline__ void mma_f16(float* c, const u32* a, const u32* b) {
    asm volatile(
        "mma.sync.aligned.m16n8k16.row.col.f32.f16.f16.f32 "
        "{%0,%1,%2,%3}, {%4,%5,%6,%7}, {%8,%9}, {%0,%1,%2,%3};"
        : "+f"(c[0]), "+f"(c[1]), "+f"(c[2]), "+f"(c[3])
        : "r"(a[0]), "r"(a[1]), "r"(a[2]), "r"(a[3]), "r"(b[0]), "r"(b[1]));
}

// C[M,N] ~= AhB + AlB (A split fp16, B single fp16), fp32 out.
// 128x128 tile, BK=32, 256 thr (4x2 warps).
#define ASTRIDE 40
#define BSTRIDE 136
__global__ void hgemm(const __half* __restrict__ Ah, const __half* __restrict__ Al,
                      const __half* __restrict__ B,
                      float* __restrict__ C, int N, int K) {
    __shared__ __half sAh[128 * ASTRIDE];
    __shared__ __half sAl[128 * ASTRIDE];
    __shared__ __half sB[32 * BSTRIDE];

    const int tid = threadIdx.x;
    const int lane = tid & 31;
    const int wid = tid >> 5;
    const int warp_m = wid & 3;
    const int warp_n = wid >> 2;
    const int cRow = blockIdx.y * 128;
    const int cCol = blockIdx.x * 128;

    const int aRow = tid >> 1;
    const int aKc = (tid & 1) * 16;
    const int bK = tid >> 3;
    const int bNc = (tid & 7) * 16;
    const __half* ApH = Ah + (size_t)(cRow + aRow) * K + aKc;
    const __half* ApL = Al + (size_t)(cRow + aRow) * K + aKc;
    const __half* Bp = B + (size_t)bK * N + cCol + bNc;

    u32 sAh_u = (u32)__cvta_generic_to_shared(sAh);
    u32 sAl_u = (u32)__cvta_generic_to_shared(sAl);
    u32 sB_u = (u32)__cvta_generic_to_shared(sB);

    float acc[2][8][4];
#pragma unroll
    for (int mt = 0; mt < 2; ++mt) {
#pragma unroll
        for (int nt = 0; nt < 8; ++nt) {
#pragma unroll
            for (int i = 0; i < 4; ++i) acc[mt][nt][i] = 0.f;
        }
    }

    const int T = K >> 5;
    for (int kt = 0; kt < T; ++kt) {
        uint4 ah0 = *(const uint4*)(ApH + (size_t)kt * 32);
        uint4 ah1 = *(const uint4*)(ApH + (size_t)kt * 32 + 8);
        uint4 al0 = *(const uint4*)(ApL + (size_t)kt * 32);
        uint4 al1 = *(const uint4*)(ApL + (size_t)kt * 32 + 8);
        uint4 b0 = *(const uint4*)(Bp + (size_t)kt * 32 * N);
        uint4 b1 = *(const uint4*)(Bp + (size_t)kt * 32 * N + 8);
        __syncthreads();
        *(uint4*)(sAh + aRow * ASTRIDE + aKc)     = ah0;
        *(uint4*)(sAh + aRow * ASTRIDE + aKc + 8) = ah1;
        *(uint4*)(sAl + aRow * ASTRIDE + aKc)     = al0;
        *(uint4*)(sAl + aRow * ASTRIDE + aKc + 8) = al1;
        *(uint4*)(sB + bK * BSTRIDE + bNc)        = b0;
        *(uint4*)(sB + bK * BSTRIDE + bNc + 8)    = b1;
        __syncthreads();

#pragma unroll
        for (int kk = 0; kk < 32; kk += 16) {
            u32 a_h[2][4];
            u32 a_l[2][4];
            u32 b_f[8][2];
#pragma unroll
            for (int mt = 0; mt < 2; ++mt) {
                int row = warp_m * 32 + mt * 16 + (lane & 15);
                u32 off = (u32)((row * ASTRIDE + kk + (lane >> 4) * 8) * 2);
                ldsm_x4(a_h[mt], sAh_u + off);
                ldsm_x4(a_l[mt], sAl_u + off);
            }
#pragma unroll
            for (int p = 0; p < 4; ++p) {
                int colbase = warp_n * 64 + p * 16;
                int krow = kk + (lane & 7) + ((lane >> 3) & 1) * 8;
                int col = colbase + ((lane >> 4) & 1) * 8;
                u32 off = (u32)((krow * BSTRIDE + col) * 2);
                u32 r[4];
                ldsm_x4t(r, sB_u + off);
                b_f[2 * p][0] = r[0];
                b_f[2 * p][1] = r[1];
                b_f[2 * p + 1][0] = r[2];
                b_f[2 * p + 1][1] = r[3];
            }
#pragma unroll
            for (int mt = 0; mt < 2; ++mt) {
#pragma unroll
                for (int nt = 0; nt < 8; ++nt) {
                    mma_f16(acc[mt][nt], a_h[mt], b_f[nt]);
                    mma_f16(acc[mt][nt], a_l[mt], b_f[nt]);
                }
            }
        }
    }

#pragma unroll
    for (int mt = 0; mt < 2; ++mt) {
#pragma unroll
        for (int nt = 0; nt < 8; ++nt) {
            int r = cRow + warp_m * 32 + mt * 16 + (lane >> 2);
            int c = cCol + warp_n * 64 + nt * 8 + (lane & 3) * 2;
            *(float2*)&C[(size_t)r * N + c] = make_float2(acc[mt][nt][0], acc[mt][nt][1]);
            *(float2*)&C[(size_t)(r + 8) * N + c] = make_float2(acc[mt][nt][2], acc[mt][nt][3]);
        }
    }
}

// ------------- feature kernel -------------
__global__ void feat_kernel() {
    const int wg = (blockIdx.x * blockDim.x + threadIdx.x) >> 5;
    const int lane = threadIdx.x & 31;
    if (wg < TOK * H_) {
        const float* src = g_q + (size_t)wg * 64;
        float x0 = src[lane];
        float x1 = src[lane + 32];
        float m = fmaxf(x0, x1);
#pragma unroll
        for (int o = 16; o; o >>= 1) m = fmaxf(m, __shfl_xor_sync(0xffffffffu, m, o));
        float e0 = __expf(x0 - m);
        float e1 = __expf(x1 - m);
        float s = e0 + e1;
#pragma unroll
        for (int o = 16; o; o >>= 1) s += __shfl_xor_sync(0xffffffffu, s, o);
        float inv = 1.f / s;
        float* dst = g_ql + (size_t)wg * 64;
        dst[lane] = e0 * inv;
        dst[lane + 32] = e1 * inv;
    } else if (wg < TOK * H_ + TOK * HKV) {
        const int r = wg - TOK * H_;
        const float* src = g_kv + (size_t)(r >> 3) * KVD + (r & 7) * 64;
        float x0 = src[lane];
        float x1 = src[lane + 32];
        float m = fmaxf(x0, x1);
#pragma unroll
        for (int o = 16; o; o >>= 1) m = fmaxf(m, __shfl_xor_sync(0xffffffffu, m, o));
        float e0 = __expf(x0 - m);
        float e1 = __expf(x1 - m);
        float s = e0 + e1;
#pragma unroll
        for (int o = 16; o; o >>= 1) s += __shfl_xor_sync(0xffffffffu, s, o);
        float inv = 1.f / s;
        float* dst = g_kl + (size_t)r * 64;
        dst[lane] = e0 * inv;
        dst[lane + 32] = e1 * inv;
        float b0 = (fminf(x0, 0.f) - log1pf(__expf(-fabsf(x0)))) * 0.0625f;
        float b1 = (fminf(x1, 0.f) - log1pf(__expf(-fabsf(x1)))) * 0.0625f;
        float* bd = g_beta + (size_t)r * 64;
        bd[lane] = b0;
        bd[lane + 32] = b1;
    }
}

// --------- delta stage 1: per-(b,h,chunk) triangular solve (grid = 1024) ---------
__global__ void delta_stage1() {
    extern __shared__ float sm[];
    float* Kc = sm;
    float* W = Kc + 64 * PAD;
    float* U = W + 64 * PAD;
    float* L = U + 64 * PAD;
    float* Q = L + 64 * PAD;

    const int tid = threadIdx.x;
    const int blk = blockIdx.x;
    const int bh = blk >> 4;
    const int ch = blk & 15;
    const int b = bh >> 5;
    const int h = bh & 31;
    const int hkv = h >> 2;
    const int e = tid & 63;
    const int r0 = (tid >> 6) * 8;
    const int n0 = ch * CHUNK;

    for (int idx = tid; idx < 4096; idx += 512) {
        int c = idx >> 6;
        int d = idx & 63;
        int t = b * N_ + n0 + c;
        float kv = g_kl[(size_t)t * KDIM + hkv * 64 + d];
        float bt = g_beta[(size_t)t * KDIM + hkv * 64 + d];
        float vv = g_kv[(size_t)t * KVD + 512 + hkv * 64 + d];
        Kc[c * PAD + d] = kv;
        W[c * PAD + d] = kv * bt;
        U[c * PAD + d] = vv * bt;
        Q[c * PAD + d] = g_ql[(size_t)t * QDIM + h * 64 + d];
    }
    __syncthreads();

    {
        float acc[8];
#pragma unroll
        for (int i = 0; i < 8; ++i) acc[i] = 0.f;
        for (int d = 0; d < 64; ++d) {
            float kb = Kc[e * PAD + d];
#pragma unroll
            for (int i = 0; i < 8; ++i) acc[i] += W[(r0 + i) * PAD + d] * kb;
        }
#pragma unroll
        for (int i = 0; i < 8; ++i) {
            L[(r0 + i) * PAD + e] = (e < r0 + i) ? acc[i] : 0.f;
        }
    }
    __syncthreads();

    for (int j = 0; j < 63; ++j) {
        float uj = U[j * PAD + e];
        float wj = W[j * PAD + e];
        for (int i = j + 1 + (tid >> 6); i < 64; i += 8) {
            float lij = L[i * PAD + j];
            U[i * PAD + e] -= lij * uj;
            W[i * PAD + e] -= lij * wj;
        }
        __syncthreads();
    }

    {
        float acc[8];
#pragma unroll
        for (int i = 0; i < 8; ++i) acc[i] = 0.f;
        for (int d = 0; d < 64; ++d) {
            float kb = Kc[e * PAD + d];
#pragma unroll
            for (int i = 0; i < 8; ++i) acc[i] += Q[(r0 + i) * PAD + d] * kb;
        }
        float* Ao = g_A + (size_t)blk * 4096;
#pragma unroll
        for (int i = 0; i < 8; ++i) {
            Ao[(r0 + i) * 64 + e] = (e <= r0 + i) ? acc[i] : 0.f;
        }
    }
    {
        float* Wo_ = g_W + (size_t)blk * 4096;
        float* Uo_ = g_U + (size_t)blk * 4096;
#pragma unroll
        for (int i = 0; i < 8; ++i) {
            Wo_[(r0 + i) * 64 + e] = W[(r0 + i) * PAD + e];
            Uo_[(r0 + i) * 64 + e] = U[(r0 + i) * PAD + e];
        }
    }
}

// --------------- tiled base causal attention: block per (i-tile, bh) -------------
__global__ void base_attn_tiled(float* __restrict__ attnw) {
    extern __shared__ float sm[];
    float* Qt = sm;
    float* Kt = Qt + 64 * PAD;
    float* Vt = Kt + 64 * PAD;
    float* Et = Vt + 64 * PAD;

    const int it = blockIdx.x;
    const int bh = blockIdx.y;
    const int b = bh >> 5;
    const int h = bh & 31;
    const int hkv = h >> 2;
    const int tid = threadIdx.x;
    const int ty = tid >> 4;
    const int tx = tid & 15;

    for (int idx = tid; idx < 4096; idx += 256) {
        int r = idx >> 6;
        int d = idx & 63;
        Qt[r * PAD + d] = g_q[(size_t)(b * N_ + it * 64 + r) * QDIM + h * 64 + d] * 0.125f;
    }

    float o[4][4];
    float rs[4];
#pragma unroll
    for (int i = 0; i < 4; ++i) {
        rs[i] = 0.f;
#pragma unroll
        for (int j = 0; j < 4; ++j) o[i][j] = 0.f;
    }

    for (int jt = 0; jt <= it; ++jt) {
        __syncthreads();
        for (int idx = tid; idx < 4096; idx += 256) {
            int r = idx >> 6;
            int d = idx & 63;
            const float* kvrow = g_kv + (size_t)(b * N_ + jt * 64 + r) * KVD + hkv * 64;
            Kt[r * PAD + d] = kvrow[d];
            Vt[r * PAD + d] = kvrow[512 + d];
        }
        __syncthreads();

        float s[4][4];
#pragma unroll
        for (int i = 0; i < 4; ++i) {
#pragma unroll
            for (int j = 0; j < 4; ++j) s[i][j] = 0.f;
        }
        for (int d = 0; d < 64; ++d) {
            float qv[4];
            float kv[4];
#pragma unroll
            for (int i = 0; i < 4; ++i) qv[i] = Qt[(ty * 4 + i) * PAD + d];
#pragma unroll
            for (int j = 0; j < 4; ++j) kv[j] = Kt[(tx * 4 + j) * PAD + d];
#pragma unroll
            for (int i = 0; i < 4; ++i) {
#pragma unroll
                for (int j = 0; j < 4; ++j) s[i][j] += qv[i] * kv[j];
            }
        }
#pragma unroll
        for (int i = 0; i < 4; ++i) {
            int gr = it * 64 + ty * 4 + i;
#pragma unroll
            for (int j = 0; j < 4; ++j) {
                int gc = jt * 64 + tx * 4 + j;
                float e = (gc <= gr) ? __expf(s[i][j]) : 0.f;
                s[i][j] = e;
                rs[i] += e;
                Et[(ty * 4 + i) * PAD + tx * 4 + j] = e;
            }
        }
        if (attnw) {
#pragma unroll
            for (int i = 0; i < 4; ++i) {
                int gr = it * 64 + ty * 4 + i;
                float4 v4 = make_float4(s[i][0], s[i][1], s[i][2], s[i][3]);
                *(float4*)&attnw[((size_t)bh * N_ + gr) * N_ + jt * 64 + tx * 4] = v4;
            }
        }
        __syncthreads();
        for (int c = 0; c < 64; ++c) {
            float ev[4];
            float vv[4];
#pragma unroll
            for (int i = 0; i < 4; ++i) ev[i] = Et[(ty * 4 + i) * PAD + c];
#pragma unroll
            for (int j = 0; j < 4; ++j) vv[j] = Vt[c * PAD + tx * 4 + j];
#pragma unroll
            for (int i = 0; i < 4; ++i) {
#pragma unroll
                for (int j = 0; j < 4; ++j) o[i][j] += ev[i] * vv[j];
            }
        }
    }

    if (attnw) {
        float4 z4 = make_float4(0.f, 0.f, 0.f, 0.f);
        for (int jt = it + 1; jt < 16; ++jt) {
#pragma unroll
            for (int i = 0; i < 4; ++i) {
                int gr = it * 64 + ty * 4 + i;
                *(float4*)&attnw[((size_t)bh * N_ + gr) * N_ + jt * 64 + tx * 4] = z4;
            }
        }
    }

#pragma unroll
    for (int i = 0; i < 4; ++i) {
#pragma unroll
        for (int off = 1; off < 16; off <<= 1) {
            rs[i] += __shfl_xor_sync(0xffffffffu, rs[i], off);
        }
    }
    float inv[4];
#pragma unroll
    for (int i = 0; i < 4; ++i) inv[i] = 1.f / rs[i];

#pragma unroll
    for (int i = 0; i < 4; ++i) {
        int gr = it * 64 + ty * 4 + i;
#pragma unroll
        for (int j = 0; j < 4; ++j) {
            g_obase[(size_t)(b * N_ + gr) * QDIM + h * 64 + tx * 4 + j] = o[i][j] * inv[i];
        }
    }

    if (attnw) {
        for (int jt = 0; jt <= it; ++jt) {
#pragma unroll
            for (int i = 0; i < 4; ++i) {
                int gr = it * 64 + ty * 4 + i;
                float* p = &attnw[((size_t)bh * N_ + gr) * N_ + jt * 64 + tx * 4];
                float4 v4 = *(float4*)p;
                v4.x *= inv[i];
                v4.y *= inv[i];
                v4.z *= inv[i];
                v4.w *= inv[i];
                *(float4*)p = v4;
            }
        }
    }
}

// --------- delta stage 2: sequential scan over chunks, per (b,h) (grid = 64) -----
__global__ void delta_stage2() {
    extern __shared__ float sm[];
    float* S = sm;
    float* W = S + 64 * PAD;
    float* U = W + 64 * PAD;
    float* A = U + 64 * PAD;
    float* Q = A + 64 * PAD;
    float* Kc = Q + 64 * PAD;

    const int tid = threadIdx.x;
    const int bh = blockIdx.x;
    const int b = bh >> 5;
    const int h = bh & 31;
    const int hkv = h >> 2;
    const int e = tid & 63;
    const int r0 = (tid >> 6) * 8;

    for (int idx = tid; idx < 4096; idx += 512) {
        S[(idx >> 6) * PAD + (idx & 63)] = 0.f;
    }
    __syncthreads();

    for (int ch = 0; ch < NC; ++ch) {
        const int n0 = ch * CHUNK;
        const size_t base = (size_t)(bh * NC + ch) * 4096;
        for (int idx = tid; idx < 4096; idx += 512) {
            int c = idx >> 6;
            int d = idx & 63;
            int t = b * N_ + n0 + c;
            W[c * PAD + d] = g_W[base + idx];
            U[c * PAD + d] = g_U[base + idx];
            A[c * PAD + d] = g_A[base + idx];
            Q[c * PAD + d] = g_ql[(size_t)t * QDIM + h * 64 + d];
            Kc[c * PAD + d] = g_kl[(size_t)t * KDIM + hkv * 64 + d];
        }
        __syncthreads();

        {
            float acc[8];
#pragma unroll
            for (int i = 0; i < 8; ++i) acc[i] = 0.f;
            for (int d = 0; d < 64; ++d) {
                float s = S[d * PAD + e];
#pragma unroll
                for (int i = 0; i < 8; ++i) acc[i] += W[(r0 + i) * PAD + d] * s;
            }
#pragma unroll
            for (int i = 0; i < 8; ++i) U[(r0 + i) * PAD + e] -= acc[i];
        }
        __syncthreads();

        {
            float acc[8];
#pragma unroll
            for (int i = 0; i < 8; ++i) acc[i] = 0.f;
            for (int d = 0; d < 64; ++d) {
                float s = S[d * PAD + e];
#pragma unroll
                for (int i = 0; i < 8; ++i) acc[i] += Q[(r0 + i) * PAD + d] * s;
            }
            for (int j = 0; j < 64; ++j) {
                float u = U[j * PAD + e];
#pragma unroll
                for (int i = 0; i < 8; ++i) acc[i] += A[(r0 + i) * PAD + j] * u;
            }
#pragma unroll
            for (int i = 0; i < 8; ++i) {
                g_olin[(size_t)(b * N_ + n0 + r0 + i) * QDIM + h * 64 + e] = acc[i];
            }
        }
        __syncthreads();

        {
            float acc[8];
#pragma unroll
            for (int i = 0; i < 8; ++i) acc[i] = 0.f;
            for (int c = 0; c < 64; ++c) {
                float u = U[c * PAD + e];
#pragma unroll
                for (int i = 0; i < 8; ++i) acc[i] += Kc[c * PAD + r0 + i] * u;
            }
#pragma unroll
            for (int i = 0; i < 8; ++i) S[(r0 + i) * PAD + e] += acc[i];
        }
        __syncthreads();
    }
}

// --------- mix 0.5*o_lin + 0.5*o_base and split to fp16 hi/lo -------------------
__global__ void split_mix() {
    int i = blockIdx.x * 256 + threadIdx.x;
    if (i < TOK * QDIM) {
        float x = 0.5f * g_obase[i] + 0.5f * g_olin[i];
        __half hv = __float2half(x);
        g_oxh[i] = hv;
        g_oxl[i] = __float2half(x - __half2float(hv));
    }
}

// ------------------------------------ launch -------------------------------------
extern "C" void kernel_launch(void* const* d_in, const int* in_sizes, int n_in,
                              void* d_out, int out_size) {
    const float* hs = (const float*)d_in[0];
    const float* Wq = (const float*)d_in[1];
    const float* Wk = (const float*)d_in[2];
    const float* Wv = (const float*)d_in[3];
    const float* Wo = (const float*)d_in[4];
    float* out = (float*)d_out;

    const size_t out_elems = (size_t)TOK * QDIM;
    const size_t attn_elems = (size_t)B_ * H_ * N_ * N_;
    float* attnw = ((size_t)out_size >= out_elems + attn_elems) ? (out + out_elems)
                                                                : (float*)0;

    float* qp;
    float* kvp;
    __half* hshp; __half* hslp;
    __half* wqp;
    __half* wkvp;
    __half* wop;
    __half* oxhp; __half* oxlp;
    cudaGetSymbolAddress((void**)&qp, g_q);
    cudaGetSymbolAddress((void**)&kvp, g_kv);
    cudaGetSymbolAddress((void**)&hshp, g_hsh);
    cudaGetSymbolAddress((void**)&hslp, g_hsl);
    cudaGetSymbolAddress((void**)&wqp, g_wq);
    cudaGetSymbolAddress((void**)&wkvp, g_wkv);
    cudaGetSymbolAddress((void**)&wop, g_wo);
    cudaGetSymbolAddress((void**)&oxhp, g_oxh);
    cudaGetSymbolAddress((void**)&oxlp, g_oxl);

    // 1: fused split/convert
    {
        const int total = SEG0 + SEG1 + SEG2 + SEG3 + SEG4;
        split_all<<<(total + 255) / 256, 256>>>(hs, Wq, Wk, Wv, Wo);
    }

    // 2-3: projections (q; fused k|v)
    hgemm<<<dim3(QDIM / 128, TOK / 128), 256>>>(hshp, hslp, wqp, qp, QDIM, HID);
    hgemm<<<dim3(KVD / 128, TOK / 128), 256>>>(hshp, hslp, wkvp, kvp, KVD, HID);

    // 4: feature maps + gate
    {
        const int total_warps = TOK * H_ + TOK * HKV;
        const int blocks = (total_warps * 32 + 255) / 256;
        feat_kernel<<<blocks, 256>>>();
    }

    // 5: delta stage 1
    cudaFuncSetAttribute(delta_stage1, cudaFuncAttributeMaxDynamicSharedMemorySize,
                         5 * 64 * PAD * (int)sizeof(float));
    delta_stage1<<<B_ * H_ * NC, 512, 5 * 64 * PAD * sizeof(float)>>>();

    // 6: base attention (profiled slot)
    cudaFuncSetAttribute(base_attn_tiled, cudaFuncAttributeMaxDynamicSharedMemorySize,
                         4 * 64 * PAD * (int)sizeof(float));
    base_attn_tiled<<<dim3(16, B_ * H_), 256, 4 * 64 * PAD * sizeof(float)>>>(attnw);

    // 7: delta stage 2
    cudaFuncSetAttribute(delta_stage2, cudaFuncAttributeMaxDynamicSharedMemorySize,
                         6 * 64 * PAD * (int)sizeof(float));
    delta_stage2<<<B_ * H_, 512, 6 * 64 * PAD * sizeof(float)>>>();

    // 8: mix + split
    split_mix<<<(TOK * QDIM + 255) / 256, 256>>>();

    // 9: output projection
    hgemm<<<dim3(HID / 128, TOK / 128), 256>>>(oxhp, oxlp, wop, out, HID, QDIM);
}